// round 1
// baseline (speedup 1.0000x reference)
#include <cuda_runtime.h>

typedef unsigned long long u64;

#define BATCH 4
#define SEQ   2048
#define EMB   1024
#define NH    16
#define HD    64
#define TOK   (BATCH*SEQ)      // 8192

// Scratch (allocation-free rule: device globals)
__device__ float g_qkv[(size_t)TOK * 3 * EMB];   // [T, 3E] == [B,S,3,H,D]
__device__ float g_att[(size_t)TOK * EMB];       // [T, E]  == [B,S,H,D]

// ---------------- packed f32x2 helpers (sm_103a FFMA2 pipe) ----------------
__device__ __forceinline__ u64 pack2(float lo, float hi) {
    u64 r; asm("mov.b64 %0, {%1, %2};" : "=l"(r) : "f"(lo), "f"(hi)); return r;
}
__device__ __forceinline__ u64 dup2(float v) { return pack2(v, v); }
__device__ __forceinline__ void fma2(u64& acc, u64 a, u64 b) {
    asm("fma.rn.f32x2 %0, %1, %2, %0;" : "+l"(acc) : "l"(a), "l"(b));
}
__device__ __forceinline__ void mul2(u64& acc, u64 a) {
    asm("mul.rn.f32x2 %0, %0, %1;" : "+l"(acc) : "l"(a));
}
__device__ __forceinline__ float2 unpack2(u64 v) {
    float2 f; asm("mov.b64 {%0, %1}, %2;" : "=f"(f.x), "=f"(f.y) : "l"(v)); return f;
}

// ---------------------------------------------------------------------------
// C[m,n] = sum_k A[m,k] * W[n,k] + bias[n]
// A: [M,K] row-major, W: [N,K] row-major (K contiguous in both).
// Tile 128x128x16, 256 threads, 8x8 per thread via f32x2.
// ---------------------------------------------------------------------------
__global__ void __launch_bounds__(256)
gemm_nt_bias(const float* __restrict__ A, const float* __restrict__ W,
             const float* __restrict__ bias, float* __restrict__ C,
             int M, int N, int K)
{
    const int BM = 128, BN = 128, BK = 16;
    __shared__ float As[16][128 + 4];
    __shared__ float Bs[16][128 + 4];

    const int tid = threadIdx.x;
    const int tx = tid & 15;         // col group
    const int ty = tid >> 4;         // row group
    const int m0 = blockIdx.y * BM;
    const int n0 = blockIdx.x * BN;

    u64 acc[8][4];
    #pragma unroll
    for (int i = 0; i < 8; i++)
        #pragma unroll
        for (int j = 0; j < 4; j++) acc[i][j] = 0ull;

    for (int k0 = 0; k0 < K; k0 += BK) {
        // Load 128x16 A tile and 128x16 W tile (transposed into smem).
        #pragma unroll
        for (int i = 0; i < 2; i++) {
            int f = tid + i * 256;          // 0..511 float4 id
            int r = f >> 2;                 // 0..127
            int c = (f & 3) << 2;           // 0,4,8,12
            float4 va = *(const float4*)(A + (size_t)(m0 + r) * K + k0 + c);
            As[c + 0][r] = va.x; As[c + 1][r] = va.y;
            As[c + 2][r] = va.z; As[c + 3][r] = va.w;
            float4 vb = *(const float4*)(W + (size_t)(n0 + r) * K + k0 + c);
            Bs[c + 0][r] = vb.x; Bs[c + 1][r] = vb.y;
            Bs[c + 2][r] = vb.z; Bs[c + 3][r] = vb.w;
        }
        __syncthreads();

        #pragma unroll
        for (int k = 0; k < BK; k++) {
            float a[8];
            *(float4*)&a[0] = *(const float4*)&As[k][ty * 8];
            *(float4*)&a[4] = *(const float4*)&As[k][ty * 8 + 4];
            const u64* bp64 = (const u64*)&Bs[k][tx * 8];
            ulonglong2 q0 = *(const ulonglong2*)(bp64);
            ulonglong2 q1 = *(const ulonglong2*)(bp64 + 2);
            u64 b2[4] = { q0.x, q0.y, q1.x, q1.y };
            u64 a2[8];
            #pragma unroll
            for (int i = 0; i < 8; i++) a2[i] = dup2(a[i]);
            #pragma unroll
            for (int i = 0; i < 8; i++)
                #pragma unroll
                for (int j = 0; j < 4; j++)
                    fma2(acc[i][j], a2[i], b2[j]);
        }
        __syncthreads();
    }

    // Epilogue: +bias, vectorized stores
    float bv[8];
    #pragma unroll
    for (int j = 0; j < 8; j++) bv[j] = bias[n0 + tx * 8 + j];

    #pragma unroll
    for (int i = 0; i < 8; i++) {
        float* cp = C + (size_t)(m0 + ty * 8 + i) * N + n0 + tx * 8;
        float2 v0 = unpack2(acc[i][0]);
        float2 v1 = unpack2(acc[i][1]);
        float2 v2 = unpack2(acc[i][2]);
        float2 v3 = unpack2(acc[i][3]);
        float4 o0 = make_float4(v0.x + bv[0], v0.y + bv[1], v1.x + bv[2], v1.y + bv[3]);
        float4 o1 = make_float4(v2.x + bv[4], v2.y + bv[5], v3.x + bv[6], v3.y + bv[7]);
        *(float4*)(cp)     = o0;
        *(float4*)(cp + 4) = o1;
    }
}

// ---------------------------------------------------------------------------
// Flash attention: one CTA = 64 queries of one (b,h). 32 key tiles of 64.
// Q,K transposed (d-major) in smem for vectorized S-GEMM; P kept in registers,
// softmax via intra-halfwarp shuffles; V reuses the K smem buffer.
// ---------------------------------------------------------------------------
__global__ void __launch_bounds__(256)
attn_kernel(const float* __restrict__ qkv, float* __restrict__ att)
{
    __shared__ float Qt[64 * 68];   // [d][q], stride 68
    __shared__ float KV[64 * 68];   // K: [d][j] stride 68; V: [j][d] stride 64

    const int tid  = threadIdx.x;
    const int tx   = tid & 15;        // key-col / d-col group (4 wide)
    const int ty   = tid >> 4;        // query-row group (4 wide)
    const int lane = tid & 31;
    const int bh = blockIdx.y;        // 0..63
    const int b  = bh >> 4;
    const int h  = bh & 15;
    const int q0 = blockIdx.x * 64;

    const size_t rs = 3 * EMB;        // token row stride in qkv
    const float* Qg = qkv + (size_t)(b * SEQ) * rs + h * HD;
    const float* Kg = Qg + EMB;
    const float* Vg = Qg + 2 * EMB;
    const float scale = 0.125f;       // 1/sqrt(64)

    // Load Q tile, transposed + pre-scaled
    #pragma unroll
    for (int i = 0; i < 4; i++) {
        int f = tid + i * 256;        // 0..1023
        int r = f >> 4;               // query row 0..63
        int d = (f & 15) << 2;
        float4 v = *(const float4*)(Qg + (size_t)(q0 + r) * rs + d);
        Qt[(d + 0) * 68 + r] = v.x * scale;
        Qt[(d + 1) * 68 + r] = v.y * scale;
        Qt[(d + 2) * 68 + r] = v.z * scale;
        Qt[(d + 3) * 68 + r] = v.w * scale;
    }

    u64 O[4][2];
    #pragma unroll
    for (int i = 0; i < 4; i++) { O[i][0] = 0ull; O[i][1] = 0ull; }
    float m_i[4], l_i[4];
    #pragma unroll
    for (int i = 0; i < 4; i++) { m_i[i] = -1e30f; l_i[i] = 0.0f; }

    for (int kt = 0; kt < SEQ / 64; kt++) {
        const int k0 = kt * 64;

        __syncthreads();              // protect KV from previous-tile PV reads
        // Load K tile transposed
        #pragma unroll
        for (int i = 0; i < 4; i++) {
            int f = tid + i * 256;
            int r = f >> 4;
            int d = (f & 15) << 2;
            float4 v = *(const float4*)(Kg + (size_t)(k0 + r) * rs + d);
            KV[(d + 0) * 68 + r] = v.x;
            KV[(d + 1) * 68 + r] = v.y;
            KV[(d + 2) * 68 + r] = v.z;
            KV[(d + 3) * 68 + r] = v.w;
        }
        __syncthreads();

        // S = (scale*Q) @ K^T : rows ty*4.., cols tx*4..
        u64 sacc[4][2];
        #pragma unroll
        for (int i = 0; i < 4; i++) { sacc[i][0] = 0ull; sacc[i][1] = 0ull; }
        #pragma unroll
        for (int d = 0; d < 64; d++) {
            float a[4];
            *(float4*)a = *(const float4*)&Qt[d * 68 + ty * 4];
            ulonglong2 bb = *(const ulonglong2*)&KV[d * 68 + tx * 4];
            #pragma unroll
            for (int i = 0; i < 4; i++) {
                u64 ad = dup2(a[i]);
                fma2(sacc[i][0], ad, bb.x);
                fma2(sacc[i][1], ad, bb.y);
            }
        }
        __syncthreads();              // S-gemm K reads done before V overwrites

        // Start V loads early (hide global latency behind softmax math)
        float4 vreg[4];
        int vr[4], vd[4];
        #pragma unroll
        for (int i = 0; i < 4; i++) {
            int f = tid + i * 256;
            vr[i] = f >> 4;
            vd[i] = (f & 15) << 2;
            vreg[i] = *(const float4*)(Vg + (size_t)(k0 + vr[i]) * rs + vd[i]);
        }

        // Online softmax (all in registers + halfwarp shuffles)
        float p[4][4];
        #pragma unroll
        for (int i = 0; i < 4; i++) {
            float2 s01 = unpack2(sacc[i][0]);
            float2 s23 = unpack2(sacc[i][1]);
            float s[4] = { s01.x, s01.y, s23.x, s23.y };
            float tm = fmaxf(fmaxf(s[0], s[1]), fmaxf(s[2], s[3]));
            #pragma unroll
            for (int o = 8; o >= 1; o >>= 1)
                tm = fmaxf(tm, __shfl_xor_sync(0xffffffffu, tm, o));
            float mnew = fmaxf(m_i[i], tm);
            float rsum = 0.0f;
            #pragma unroll
            for (int jq = 0; jq < 4; jq++) {
                p[i][jq] = __expf(s[jq] - mnew);
                rsum += p[i][jq];
            }
            #pragma unroll
            for (int o = 8; o >= 1; o >>= 1)
                rsum += __shfl_xor_sync(0xffffffffu, rsum, o);
            float al = __expf(m_i[i] - mnew);
            l_i[i] = l_i[i] * al + rsum;
            m_i[i] = mnew;
            u64 a2 = dup2(al);
            mul2(O[i][0], a2);
            mul2(O[i][1], a2);
        }

        // Commit V into smem (natural [j][d] layout, stride 64)
        #pragma unroll
        for (int i = 0; i < 4; i++)
            *(float4*)&KV[vr[i] * 64 + vd[i]] = vreg[i];
        __syncthreads();

        // O += P @ V  (P fetched from owning lanes via shuffle)
        #pragma unroll
        for (int jo = 0; jo < 16; jo++) {
            #pragma unroll
            for (int jq = 0; jq < 4; jq++) {
                int j = jo * 4 + jq;
                ulonglong2 vv = *(const ulonglong2*)&KV[j * 64 + tx * 4];
                int src = (lane & 16) | jo;
                float p0 = __shfl_sync(0xffffffffu, p[0][jq], src);
                float p1 = __shfl_sync(0xffffffffu, p[1][jq], src);
                float p2 = __shfl_sync(0xffffffffu, p[2][jq], src);
                float p3 = __shfl_sync(0xffffffffu, p[3][jq], src);
                u64 d0 = dup2(p0), d1 = dup2(p1), d2 = dup2(p2), d3 = dup2(p3);
                fma2(O[0][0], d0, vv.x); fma2(O[0][1], d0, vv.y);
                fma2(O[1][0], d1, vv.x); fma2(O[1][1], d1, vv.y);
                fma2(O[2][0], d2, vv.x); fma2(O[2][1], d2, vv.y);
                fma2(O[3][0], d3, vv.x); fma2(O[3][1], d3, vv.y);
            }
        }
    }

    // Normalize and write: att[(b*S + q0 + r), h*HD + c]
    #pragma unroll
    for (int i = 0; i < 4; i++) {
        int r = ty * 4 + i;
        float inv = 1.0f / l_i[i];
        float2 v0 = unpack2(O[i][0]);
        float2 v1 = unpack2(O[i][1]);
        float4 st = make_float4(v0.x * inv, v0.y * inv, v1.x * inv, v1.y * inv);
        *(float4*)(att + (size_t)(b * SEQ + q0 + r) * EMB + h * HD + tx * 4) = st;
    }
}

// ---------------------------------------------------------------------------
extern "C" void kernel_launch(void* const* d_in, const int* in_sizes, int n_in,
                              void* d_out, int out_size)
{
    const float* x      = (const float*)d_in[0];
    const float* w_qkv  = (const float*)d_in[1];
    const float* b_qkv  = (const float*)d_in[2];
    const float* w_proj = (const float*)d_in[3];
    const float* b_proj = (const float*)d_in[4];
    float* out = (float*)d_out;

    float* qkv_ptr = nullptr;
    float* att_ptr = nullptr;
    cudaGetSymbolAddress((void**)&qkv_ptr, g_qkv);
    cudaGetSymbolAddress((void**)&att_ptr, g_att);

    // 1) QKV projection: [8192,1024] x [3072,1024]^T + b -> [8192,3072]
    dim3 g1(3 * EMB / 128, TOK / 128);
    gemm_nt_bias<<<g1, 256>>>(x, w_qkv, b_qkv, qkv_ptr, TOK, 3 * EMB, EMB);

    // 2) Attention: 64 (b,h) instances, 32 query tiles each
    dim3 g2(SEQ / 64, BATCH * NH);
    attn_kernel<<<g2, 256>>>(qkv_ptr, att_ptr);

    // 3) Output projection: [8192,1024] x [1024,1024]^T + b -> out
    dim3 g3(EMB / 128, TOK / 128);
    gemm_nt_bias<<<g3, 256>>>(att_ptr, w_proj, b_proj, out, TOK, EMB, EMB);
}

// round 3
// speedup vs baseline: 1.2375x; 1.2375x over previous
#include <cuda_runtime.h>
#include <cuda_bf16.h>
#include <cstdint>

typedef unsigned long long u64;

#define BATCH 4
#define SEQ   2048
#define EMB   1024
#define NH    16
#define HD    64
#define TOK   (BATCH*SEQ)      // 8192

// Scratch (allocation-free rule: device globals)
__device__ float g_qkv[(size_t)TOK * 3 * EMB];   // [T, 3E] == [B,S,3,H,D]
__device__ float g_att[(size_t)TOK * EMB];       // [T, E]  == [B,S,H,D]

// ---------------- packed f32x2 helpers (attention kernel) ----------------
__device__ __forceinline__ u64 pack2(float lo, float hi) {
    u64 r; asm("mov.b64 %0, {%1, %2};" : "=l"(r) : "f"(lo), "f"(hi)); return r;
}
__device__ __forceinline__ u64 dup2(float v) { return pack2(v, v); }
__device__ __forceinline__ void fma2(u64& acc, u64 a, u64 b) {
    asm("fma.rn.f32x2 %0, %1, %2, %0;" : "+l"(acc) : "l"(a), "l"(b));
}
__device__ __forceinline__ void mul2(u64& acc, u64 a) {
    asm("mul.rn.f32x2 %0, %0, %1;" : "+l"(acc) : "l"(a));
}
__device__ __forceinline__ float2 unpack2(u64 v) {
    float2 f; asm("mov.b64 {%0, %1}, %2;" : "=f"(f.x), "=f"(f.y) : "l"(v)); return f;
}

// ---------------- HMMA (mma.sync) primitives — baseline PTX, no 'a' needed --
__device__ __forceinline__ uint32_t smem_u32(const void* p) {
    uint32_t a;
    asm("{ .reg .u64 t; cvta.to.shared.u64 t, %1; cvt.u32.u64 %0, t; }" : "=r"(a) : "l"(p));
    return a;
}
__device__ __forceinline__ void ldm_x4(uint32_t* r, uint32_t addr) {
    asm volatile("ldmatrix.sync.aligned.m8n8.x4.shared.b16 {%0,%1,%2,%3}, [%4];"
        : "=r"(r[0]), "=r"(r[1]), "=r"(r[2]), "=r"(r[3]) : "r"(addr));
}
__device__ __forceinline__ void mma16816(float* c, const uint32_t* a, const uint32_t* b) {
    asm volatile(
        "mma.sync.aligned.m16n8k16.row.col.f32.bf16.bf16.f32 "
        "{%0,%1,%2,%3}, {%4,%5,%6,%7}, {%8,%9}, {%0,%1,%2,%3};"
        : "+f"(c[0]), "+f"(c[1]), "+f"(c[2]), "+f"(c[3])
        : "r"(a[0]), "r"(a[1]), "r"(a[2]), "r"(a[3]), "r"(b[0]), "r"(b[1]));
}

// split a float4 into hi/lo bf16x4 (8B each); memory order preserved
__device__ __forceinline__ void cvt_split(float4 v, uint2& hi, uint2& lo) {
    __nv_bfloat162 h0 = __floats2bfloat162_rn(v.x, v.y);
    __nv_bfloat162 h1 = __floats2bfloat162_rn(v.z, v.w);
    float rx = __bfloat162float(h0.x), ry = __bfloat162float(h0.y);
    float rz = __bfloat162float(h1.x), rw = __bfloat162float(h1.y);
    __nv_bfloat162 l0 = __floats2bfloat162_rn(v.x - rx, v.y - ry);
    __nv_bfloat162 l1 = __floats2bfloat162_rn(v.z - rz, v.w - rw);
    hi.x = *(uint32_t*)&h0; hi.y = *(uint32_t*)&h1;
    lo.x = *(uint32_t*)&l0; lo.y = *(uint32_t*)&l1;
}

// smem geometry: rows of 32 bf16 padded to 40 (80 bytes) -> conflict-free
#define ROWB   80
#define MAT_B  (128 * ROWB)      // 10240 per matrix-half
#define S_AH   0
#define S_AL   (1 * MAT_B)
#define S_BH   (2 * MAT_B)
#define S_BL   (3 * MAT_B)
#define BUF_B  (4 * MAT_B)       // 40960
#define GEMM_SMEM (2 * BUF_B)    // 81920

// ---------------------------------------------------------------------------
// C[m,n] = sum_k A[m,k]*W[n,k] + bias[n]  via HMMA bf16x3 split.
// CTA 128x128, BK=32, 8 warps (4m x 2n), warp tile 32x64.
// ---------------------------------------------------------------------------
__global__ void __launch_bounds__(256)
gemm_hmma(const float* __restrict__ A, const float* __restrict__ W,
          const float* __restrict__ bias, float* __restrict__ C,
          int M, int N, int K)
{
    extern __shared__ __align__(128) char smem[];
    const uint32_t sb = smem_u32(smem);
    const int tid = threadIdx.x;
    const int lane = tid & 31, wid = tid >> 5;
    const int wm = wid >> 1, wn = wid & 1;        // 4 x 2 warp grid
    const int m0 = blockIdx.y * 128;
    const int n0 = blockIdx.x * 128;

    float acc[2][8][4];
    #pragma unroll
    for (int mt = 0; mt < 2; mt++)
        #pragma unroll
        for (int nt = 0; nt < 8; nt++)
            #pragma unroll
            for (int q = 0; q < 4; q++) acc[mt][nt][q] = 0.0f;

    // fragment smem addresses (ldmatrix lane addressing)
    const int frow = lane & 15;                 // row within 16-row tile
    const int fcol = ((lane >> 4) & 1) * 16;    // 16B column half
    // A tiles: rows wm*32 + mt*16; B tiles: rows wn*64 + ntp*16
    uint32_t a_addr[2], b_addr[4];
    #pragma unroll
    for (int mt = 0; mt < 2; mt++)
        a_addr[mt] = (uint32_t)((wm * 32 + mt * 16 + frow) * ROWB + fcol);
    #pragma unroll
    for (int p = 0; p < 4; p++)
        b_addr[p] = (uint32_t)((wn * 64 + p * 16 + frow) * ROWB + fcol);

    // global staging
    float4 stA[4], stB[4];
    const int r_ld = tid >> 3;           // 0..31 (+32 per j)
    const int seg  = tid & 7;            // 0..7 -> 4 floats each

    auto ldg = [&](int k0) {
        #pragma unroll
        for (int j = 0; j < 4; j++) {
            int r = r_ld + j * 32;
            stA[j] = *(const float4*)(A + (size_t)(m0 + r) * K + k0 + seg * 4);
            stB[j] = *(const float4*)(W + (size_t)(n0 + r) * K + k0 + seg * 4);
        }
    };
    auto sts = [&](int buf) {
        char* b = smem + buf * BUF_B;
        #pragma unroll
        for (int j = 0; j < 4; j++) {
            int r = r_ld + j * 32;
            uint32_t off = (uint32_t)(r * ROWB + seg * 8);
            uint2 hi, lo;
            cvt_split(stA[j], hi, lo);
            *(uint2*)(b + S_AH + off) = hi;
            *(uint2*)(b + S_AL + off) = lo;
            cvt_split(stB[j], hi, lo);
            *(uint2*)(b + S_BH + off) = hi;
            *(uint2*)(b + S_BL + off) = lo;
        }
    };

    const int nch = K / 32;
    ldg(0);
    sts(0);
    __syncthreads();

    for (int i = 0; i < nch; i++) {
        if (i + 1 < nch) ldg((i + 1) * 32);

        const uint32_t base = sb + (i & 1) * BUF_B;
        #pragma unroll
        for (int kh = 0; kh < 2; kh++) {
            const uint32_t kb = kh * 32;   // 16 bf16 = 32B column offset
            uint32_t ah[2][4], al[2][4], bh[4][4], bl[4][4];
            #pragma unroll
            for (int mt = 0; mt < 2; mt++) {
                ldm_x4(ah[mt], base + S_AH + a_addr[mt] + kb);
                ldm_x4(al[mt], base + S_AL + a_addr[mt] + kb);
            }
            #pragma unroll
            for (int p = 0; p < 4; p++) {
                ldm_x4(bh[p], base + S_BH + b_addr[p] + kb);
                ldm_x4(bl[p], base + S_BL + b_addr[p] + kb);
            }
            // bh[p] regs: {b0(nt=2p), b0(nt=2p+1), b1(nt=2p), b1(nt=2p+1)}
            #pragma unroll
            for (int mt = 0; mt < 2; mt++) {
                #pragma unroll
                for (int p = 0; p < 4; p++) {
                    uint32_t b0h[2] = { bh[p][0], bh[p][2] };
                    uint32_t b1h[2] = { bh[p][1], bh[p][3] };
                    uint32_t b0l[2] = { bl[p][0], bl[p][2] };
                    uint32_t b1l[2] = { bl[p][1], bl[p][3] };
                    mma16816(acc[mt][2*p+0], ah[mt], b0h);
                    mma16816(acc[mt][2*p+1], ah[mt], b1h);
                    mma16816(acc[mt][2*p+0], ah[mt], b0l);
                    mma16816(acc[mt][2*p+1], ah[mt], b1l);
                    mma16816(acc[mt][2*p+0], al[mt], b0h);
                    mma16816(acc[mt][2*p+1], al[mt], b1h);
                }
            }
        }

        if (i + 1 < nch) sts((i + 1) & 1);
        __syncthreads();
    }

    // epilogue: +bias, float2 stores
    const int g = lane >> 2, t = lane & 3;
    #pragma unroll
    for (int mt = 0; mt < 2; mt++) {
        int row = m0 + wm * 32 + mt * 16 + g;
        #pragma unroll
        for (int nt = 0; nt < 8; nt++) {
            int col = n0 + wn * 64 + nt * 8 + t * 2;
            float bx = bias[col], by = bias[col + 1];
            float* c = acc[mt][nt];
            *(float2*)(C + (size_t)row * N + col) =
                make_float2(c[0] + bx, c[1] + by);
            *(float2*)(C + (size_t)(row + 8) * N + col) =
                make_float2(c[2] + bx, c[3] + by);
        }
    }
}

// ---------------------------------------------------------------------------
// Flash attention (unchanged, known-good): one CTA = 64 queries of one (b,h).
// ---------------------------------------------------------------------------
__global__ void __launch_bounds__(256)
attn_kernel(const float* __restrict__ qkv, float* __restrict__ att)
{
    __shared__ float Qt[64 * 68];   // [d][q], stride 68
    __shared__ float KV[64 * 68];   // K: [d][j] stride 68; V: [j][d] stride 64

    const int tid  = threadIdx.x;
    const int tx   = tid & 15;
    const int ty   = tid >> 4;
    const int lane = tid & 31;
    const int bh = blockIdx.y;
    const int b  = bh >> 4;
    const int h  = bh & 15;
    const int q0 = blockIdx.x * 64;

    const size_t rs = 3 * EMB;
    const float* Qg = qkv + (size_t)(b * SEQ) * rs + h * HD;
    const float* Kg = Qg + EMB;
    const float* Vg = Qg + 2 * EMB;
    const float scale = 0.125f;

    #pragma unroll
    for (int i = 0; i < 4; i++) {
        int f = tid + i * 256;
        int r = f >> 4;
        int d = (f & 15) << 2;
        float4 v = *(const float4*)(Qg + (size_t)(q0 + r) * rs + d);
        Qt[(d + 0) * 68 + r] = v.x * scale;
        Qt[(d + 1) * 68 + r] = v.y * scale;
        Qt[(d + 2) * 68 + r] = v.z * scale;
        Qt[(d + 3) * 68 + r] = v.w * scale;
    }

    u64 O[4][2];
    #pragma unroll
    for (int i = 0; i < 4; i++) { O[i][0] = 0ull; O[i][1] = 0ull; }
    float m_i[4], l_i[4];
    #pragma unroll
    for (int i = 0; i < 4; i++) { m_i[i] = -1e30f; l_i[i] = 0.0f; }

    for (int kt = 0; kt < SEQ / 64; kt++) {
        const int k0 = kt * 64;

        __syncthreads();
        #pragma unroll
        for (int i = 0; i < 4; i++) {
            int f = tid + i * 256;
            int r = f >> 4;
            int d = (f & 15) << 2;
            float4 v = *(const float4*)(Kg + (size_t)(k0 + r) * rs + d);
            KV[(d + 0) * 68 + r] = v.x;
            KV[(d + 1) * 68 + r] = v.y;
            KV[(d + 2) * 68 + r] = v.z;
            KV[(d + 3) * 68 + r] = v.w;
        }
        __syncthreads();

        u64 sacc[4][2];
        #pragma unroll
        for (int i = 0; i < 4; i++) { sacc[i][0] = 0ull; sacc[i][1] = 0ull; }
        #pragma unroll
        for (int d = 0; d < 64; d++) {
            float a[4];
            *(float4*)a = *(const float4*)&Qt[d * 68 + ty * 4];
            ulonglong2 bb = *(const ulonglong2*)&KV[d * 68 + tx * 4];
            #pragma unroll
            for (int i = 0; i < 4; i++) {
                u64 ad = dup2(a[i]);
                fma2(sacc[i][0], ad, bb.x);
                fma2(sacc[i][1], ad, bb.y);
            }
        }
        __syncthreads();

        float4 vreg[4];
        int vr[4], vd[4];
        #pragma unroll
        for (int i = 0; i < 4; i++) {
            int f = tid + i * 256;
            vr[i] = f >> 4;
            vd[i] = (f & 15) << 2;
            vreg[i] = *(const float4*)(Vg + (size_t)(k0 + vr[i]) * rs + vd[i]);
        }

        float p[4][4];
        #pragma unroll
        for (int i = 0; i < 4; i++) {
            float2 s01 = unpack2(sacc[i][0]);
            float2 s23 = unpack2(sacc[i][1]);
            float s[4] = { s01.x, s01.y, s23.x, s23.y };
            float tm = fmaxf(fmaxf(s[0], s[1]), fmaxf(s[2], s[3]));
            #pragma unroll
            for (int o = 8; o >= 1; o >>= 1)
                tm = fmaxf(tm, __shfl_xor_sync(0xffffffffu, tm, o));
            float mnew = fmaxf(m_i[i], tm);
            float rsum = 0.0f;
            #pragma unroll
            for (int jq = 0; jq < 4; jq++) {
                p[i][jq] = __expf(s[jq] - mnew);
                rsum += p[i][jq];
            }
            #pragma unroll
            for (int o = 8; o >= 1; o >>= 1)
                rsum += __shfl_xor_sync(0xffffffffu, rsum, o);
            float al = __expf(m_i[i] - mnew);
            l_i[i] = l_i[i] * al + rsum;
            m_i[i] = mnew;
            u64 a2 = dup2(al);
            mul2(O[i][0], a2);
            mul2(O[i][1], a2);
        }

        #pragma unroll
        for (int i = 0; i < 4; i++)
            *(float4*)&KV[vr[i] * 64 + vd[i]] = vreg[i];
        __syncthreads();

        #pragma unroll
        for (int jo = 0; jo < 16; jo++) {
            #pragma unroll
            for (int jq = 0; jq < 4; jq++) {
                int j = jo * 4 + jq;
                ulonglong2 vv = *(const ulonglong2*)&KV[j * 64 + tx * 4];
                int src = (lane & 16) | jo;
                float p0 = __shfl_sync(0xffffffffu, p[0][jq], src);
                float p1 = __shfl_sync(0xffffffffu, p[1][jq], src);
                float p2 = __shfl_sync(0xffffffffu, p[2][jq], src);
                float p3 = __shfl_sync(0xffffffffu, p[3][jq], src);
                u64 d0 = dup2(p0), d1 = dup2(p1), d2 = dup2(p2), d3 = dup2(p3);
                fma2(O[0][0], d0, vv.x); fma2(O[0][1], d0, vv.y);
                fma2(O[1][0], d1, vv.x); fma2(O[1][1], d1, vv.y);
                fma2(O[2][0], d2, vv.x); fma2(O[2][1], d2, vv.y);
                fma2(O[3][0], d3, vv.x); fma2(O[3][1], d3, vv.y);
            }
        }
    }

    #pragma unroll
    for (int i = 0; i < 4; i++) {
        int r = ty * 4 + i;
        float inv = 1.0f / l_i[i];
        float2 v0 = unpack2(O[i][0]);
        float2 v1 = unpack2(O[i][1]);
        float4 st = make_float4(v0.x * inv, v0.y * inv, v1.x * inv, v1.y * inv);
        *(float4*)(att + (size_t)(b * SEQ + q0 + r) * EMB + h * HD + tx * 4) = st;
    }
}

// ---------------------------------------------------------------------------
extern "C" void kernel_launch(void* const* d_in, const int* in_sizes, int n_in,
                              void* d_out, int out_size)
{
    const float* x      = (const float*)d_in[0];
    const float* w_qkv  = (const float*)d_in[1];
    const float* b_qkv  = (const float*)d_in[2];
    const float* w_proj = (const float*)d_in[3];
    const float* b_proj = (const float*)d_in[4];
    float* out = (float*)d_out;

    float* qkv_ptr = nullptr;
    float* att_ptr = nullptr;
    cudaGetSymbolAddress((void**)&qkv_ptr, g_qkv);
    cudaGetSymbolAddress((void**)&att_ptr, g_att);

    cudaFuncSetAttribute(gemm_hmma, cudaFuncAttributeMaxDynamicSharedMemorySize, GEMM_SMEM);

    // 1) QKV projection: [8192,1024] x [3072,1024]^T + b -> [8192,3072]
    dim3 g1(3 * EMB / 128, TOK / 128);
    gemm_hmma<<<g1, 256, GEMM_SMEM>>>(x, w_qkv, b_qkv, qkv_ptr, TOK, 3 * EMB, EMB);

    // 2) Attention: 64 (b,h) instances, 32 query tiles each
    dim3 g2(SEQ / 64, BATCH * NH);
    attn_kernel<<<g2, 256>>>(qkv_ptr, att_ptr);

    // 3) Output projection: [8192,1024] x [1024,1024]^T + b -> out
    dim3 g3(EMB / 128, TOK / 128);
    gemm_hmma<<<g3, 256, GEMM_SMEM>>>(att_ptr, w_proj, b_proj, out, TOK, EMB, EMB);
}

// round 4
// speedup vs baseline: 2.1369x; 1.7268x over previous
#include <cuda_runtime.h>
#include <cuda_bf16.h>
#include <cstdint>

typedef unsigned long long u64;

#define BATCH 4
#define SEQ   2048
#define EMB   1024
#define NH    16
#define HD    64
#define TOK   (BATCH*SEQ)      // 8192

// Scratch (allocation-free rule: device globals)
__device__ float g_qkv[(size_t)TOK * 3 * EMB];   // [T, 3E] == [B,S,3,H,D]
__device__ float g_att[(size_t)TOK * EMB];       // [T, E]  == [B,S,H,D]

// ---------------- HMMA (mma.sync) primitives — baseline PTX ----------------
__device__ __forceinline__ uint32_t smem_u32(const void* p) {
    uint32_t a;
    asm("{ .reg .u64 t; cvta.to.shared.u64 t, %1; cvt.u32.u64 %0, t; }" : "=r"(a) : "l"(p));
    return a;
}
__device__ __forceinline__ void ldm_x4(uint32_t* r, uint32_t addr) {
    asm volatile("ldmatrix.sync.aligned.m8n8.x4.shared.b16 {%0,%1,%2,%3}, [%4];"
        : "=r"(r[0]), "=r"(r[1]), "=r"(r[2]), "=r"(r[3]) : "r"(addr));
}
__device__ __forceinline__ void mma16816(float* c, const uint32_t* a, const uint32_t* b) {
    asm volatile(
        "mma.sync.aligned.m16n8k16.row.col.f32.bf16.bf16.f32 "
        "{%0,%1,%2,%3}, {%4,%5,%6,%7}, {%8,%9}, {%0,%1,%2,%3};"
        : "+f"(c[0]), "+f"(c[1]), "+f"(c[2]), "+f"(c[3])
        : "r"(a[0]), "r"(a[1]), "r"(a[2]), "r"(a[3]), "r"(b[0]), "r"(b[1]));
}

// split float4 -> hi/lo bf16x4 (8B each), memory order preserved
__device__ __forceinline__ void cvt_split(float4 v, uint2& hi, uint2& lo) {
    __nv_bfloat162 h0 = __floats2bfloat162_rn(v.x, v.y);
    __nv_bfloat162 h1 = __floats2bfloat162_rn(v.z, v.w);
    float rx = __bfloat162float(h0.x), ry = __bfloat162float(h0.y);
    float rz = __bfloat162float(h1.x), rw = __bfloat162float(h1.y);
    __nv_bfloat162 l0 = __floats2bfloat162_rn(v.x - rx, v.y - ry);
    __nv_bfloat162 l1 = __floats2bfloat162_rn(v.z - rz, v.w - rw);
    hi.x = *(uint32_t*)&h0; hi.y = *(uint32_t*)&h1;
    lo.x = *(uint32_t*)&l0; lo.y = *(uint32_t*)&l1;
}
__device__ __forceinline__ void split2(float x, float y, uint32_t& h, uint32_t& l) {
    __nv_bfloat162 hh = __floats2bfloat162_rn(x, y);
    h = *(uint32_t*)&hh;
    __nv_bfloat162 ll = __floats2bfloat162_rn(x - __bfloat162float(hh.x),
                                              y - __bfloat162float(hh.y));
    l = *(uint32_t*)&ll;
}

// ================= GEMM (unchanged from round 3, known-good) =================
#define ROWB   80
#define MAT_B  (128 * ROWB)
#define S_AH   0
#define S_AL   (1 * MAT_B)
#define S_BH   (2 * MAT_B)
#define S_BL   (3 * MAT_B)
#define BUF_B  (4 * MAT_B)
#define GEMM_SMEM (2 * BUF_B)

__global__ void __launch_bounds__(256)
gemm_hmma(const float* __restrict__ A, const float* __restrict__ W,
          const float* __restrict__ bias, float* __restrict__ C,
          int M, int N, int K)
{
    extern __shared__ __align__(128) char smem[];
    const uint32_t sb = smem_u32(smem);
    const int tid = threadIdx.x;
    const int lane = tid & 31, wid = tid >> 5;
    const int wm = wid >> 1, wn = wid & 1;
    const int m0 = blockIdx.y * 128;
    const int n0 = blockIdx.x * 128;

    float acc[2][8][4];
    #pragma unroll
    for (int mt = 0; mt < 2; mt++)
        #pragma unroll
        for (int nt = 0; nt < 8; nt++)
            #pragma unroll
            for (int q = 0; q < 4; q++) acc[mt][nt][q] = 0.0f;

    const int frow = lane & 15;
    const int fcol = ((lane >> 4) & 1) * 16;
    uint32_t a_addr[2], b_addr[4];
    #pragma unroll
    for (int mt = 0; mt < 2; mt++)
        a_addr[mt] = (uint32_t)((wm * 32 + mt * 16 + frow) * ROWB + fcol);
    #pragma unroll
    for (int p = 0; p < 4; p++)
        b_addr[p] = (uint32_t)((wn * 64 + p * 16 + frow) * ROWB + fcol);

    float4 stA[4], stB[4];
    const int r_ld = tid >> 3;
    const int seg  = tid & 7;

    auto ldg = [&](int k0) {
        #pragma unroll
        for (int j = 0; j < 4; j++) {
            int r = r_ld + j * 32;
            stA[j] = *(const float4*)(A + (size_t)(m0 + r) * K + k0 + seg * 4);
            stB[j] = *(const float4*)(W + (size_t)(n0 + r) * K + k0 + seg * 4);
        }
    };
    auto sts = [&](int buf) {
        char* b = smem + buf * BUF_B;
        #pragma unroll
        for (int j = 0; j < 4; j++) {
            int r = r_ld + j * 32;
            uint32_t off = (uint32_t)(r * ROWB + seg * 8);
            uint2 hi, lo;
            cvt_split(stA[j], hi, lo);
            *(uint2*)(b + S_AH + off) = hi;
            *(uint2*)(b + S_AL + off) = lo;
            cvt_split(stB[j], hi, lo);
            *(uint2*)(b + S_BH + off) = hi;
            *(uint2*)(b + S_BL + off) = lo;
        }
    };

    const int nch = K / 32;
    ldg(0);
    sts(0);
    __syncthreads();

    for (int i = 0; i < nch; i++) {
        if (i + 1 < nch) ldg((i + 1) * 32);

        const uint32_t base = sb + (i & 1) * BUF_B;
        #pragma unroll
        for (int kh = 0; kh < 2; kh++) {
            const uint32_t kb = kh * 32;
            uint32_t ah[2][4], al[2][4], bh[4][4], bl[4][4];
            #pragma unroll
            for (int mt = 0; mt < 2; mt++) {
                ldm_x4(ah[mt], base + S_AH + a_addr[mt] + kb);
                ldm_x4(al[mt], base + S_AL + a_addr[mt] + kb);
            }
            #pragma unroll
            for (int p = 0; p < 4; p++) {
                ldm_x4(bh[p], base + S_BH + b_addr[p] + kb);
                ldm_x4(bl[p], base + S_BL + b_addr[p] + kb);
            }
            #pragma unroll
            for (int mt = 0; mt < 2; mt++) {
                #pragma unroll
                for (int p = 0; p < 4; p++) {
                    uint32_t b0h[2] = { bh[p][0], bh[p][2] };
                    uint32_t b1h[2] = { bh[p][1], bh[p][3] };
                    uint32_t b0l[2] = { bl[p][0], bl[p][2] };
                    uint32_t b1l[2] = { bl[p][1], bl[p][3] };
                    mma16816(acc[mt][2*p+0], ah[mt], b0h);
                    mma16816(acc[mt][2*p+1], ah[mt], b1h);
                    mma16816(acc[mt][2*p+0], ah[mt], b0l);
                    mma16816(acc[mt][2*p+1], ah[mt], b1l);
                    mma16816(acc[mt][2*p+0], al[mt], b0h);
                    mma16816(acc[mt][2*p+1], al[mt], b1h);
                }
            }
        }

        if (i + 1 < nch) sts((i + 1) & 1);
        __syncthreads();
    }

    const int g = lane >> 2, t = lane & 3;
    #pragma unroll
    for (int mt = 0; mt < 2; mt++) {
        int row = m0 + wm * 32 + mt * 16 + g;
        #pragma unroll
        for (int nt = 0; nt < 8; nt++) {
            int col = n0 + wn * 64 + nt * 8 + t * 2;
            float bx = bias[col], by = bias[col + 1];
            float* c = acc[mt][nt];
            *(float2*)(C + (size_t)row * N + col) =
                make_float2(c[0] + bx, c[1] + by);
            *(float2*)(C + (size_t)(row + 8) * N + col) =
                make_float2(c[2] + bx, c[3] + by);
        }
    }
}

// ================= HMMA flash attention =================
// CTA = 128 queries of one (b,h); 16 key tiles of 128.
// 8 warps; warp w owns query rows w*16..w*16+15 -> softmax fully warp-local.
#define KSTR 144                       // Q/K row bytes (64 bf16 + pad)
#define VSTR 272                       // Vt row bytes (128 bf16 + pad)
#define AS_QH 0
#define AS_QL (AS_QH + 128*KSTR)
#define AS_KH (AS_QL + 128*KSTR)
#define AS_KL (AS_KH + 128*KSTR)
#define AS_VH (AS_KL + 128*KSTR)
#define AS_VL (AS_VH + 64*VSTR)
#define ATT_SMEM (AS_VL + 64*VSTR)     // 108544 bytes

__global__ void __launch_bounds__(256)
attn_hmma(const float* __restrict__ qkv, float* __restrict__ att)
{
    extern __shared__ __align__(128) char smem[];
    const uint32_t sb = smem_u32(smem);
    const int tid = threadIdx.x;
    const int lane = tid & 31, wid = tid >> 5;
    const int b = blockIdx.y >> 4, h = blockIdx.y & 15;
    const int q0 = blockIdx.x * 128;

    const size_t rs = 3 * EMB;
    const float* Qg = qkv + (size_t)(b * SEQ) * rs + h * HD;
    const float* Kg = Qg + EMB;
    const float* Vg = Qg + 2 * EMB;

    // ---- load Q once (pre-scaled by 1/8, exact), split to hi/lo ----
    #pragma unroll
    for (int i = 0; i < 8; i++) {
        int idx = tid + i * 256;            // 0..2047
        int r = idx >> 4, seg = idx & 15;
        float4 v = *(const float4*)(Qg + (size_t)(q0 + r) * rs + seg * 4);
        v.x *= 0.125f; v.y *= 0.125f; v.z *= 0.125f; v.w *= 0.125f;
        uint2 hi, lo;
        cvt_split(v, hi, lo);
        *(uint2*)(smem + AS_QH + r * KSTR + seg * 8) = hi;
        *(uint2*)(smem + AS_QL + r * KSTR + seg * 8) = lo;
    }

    // fragment addresses
    const int frow = lane & 15;
    const int fcol = ((lane >> 4) & 1) * 16;
    const uint32_t qa = sb + AS_QH + (uint32_t)((wid * 16 + frow) * KSTR + fcol);
    const uint32_t ka = sb + AS_KH + (uint32_t)(frow * KSTR + fcol);
    const uint32_t va = sb + AS_VH + (uint32_t)(frow * VSTR + fcol);
    const uint32_t QLO = AS_QL - AS_QH;
    const uint32_t KLO = AS_KL - AS_KH;
    const uint32_t VLO = AS_VL - AS_VH;

    float oacc[8][4];
    #pragma unroll
    for (int nt = 0; nt < 8; nt++)
        #pragma unroll
        for (int q = 0; q < 4; q++) oacc[nt][q] = 0.0f;
    float m0 = -1e30f, m1 = -1e30f;     // running max for rows g, g+8
    float l0 = 0.0f, l1 = 0.0f;         // per-thread partial row sums

    for (int kt = 0; kt < SEQ / 128; kt++) {
        const int k0 = kt * 128;
        __syncthreads();  // smem reuse safe (prev iter mma reads done)

        // ---- load K tile [128 keys x 64 d] ----
        #pragma unroll
        for (int i = 0; i < 8; i++) {
            int idx = tid + i * 256;
            int r = idx >> 4, seg = idx & 15;
            float4 v = *(const float4*)(Kg + (size_t)(k0 + r) * rs + seg * 4);
            uint2 hi, lo;
            cvt_split(v, hi, lo);
            *(uint2*)(smem + AS_KH + r * KSTR + seg * 8) = hi;
            *(uint2*)(smem + AS_KL + r * KSTR + seg * 8) = lo;
        }
        // ---- load V tile transposed -> Vt[d][key] ----
        #pragma unroll
        for (int i = 0; i < 8; i++) {
            int idx = tid + i * 256;
            int key = idx >> 4, seg = idx & 15;
            float4 v = *(const float4*)(Vg + (size_t)(k0 + key) * rs + seg * 4);
            float f[4] = { v.x, v.y, v.z, v.w };
            #pragma unroll
            for (int j = 0; j < 4; j++) {
                __nv_bfloat16 hv = __float2bfloat16(f[j]);
                __nv_bfloat16 lv = __float2bfloat16(f[j] - __bfloat162float(hv));
                int d = seg * 4 + j;
                *(__nv_bfloat16*)(smem + AS_VH + d * VSTR + key * 2) = hv;
                *(__nv_bfloat16*)(smem + AS_VL + d * VSTR + key * 2) = lv;
            }
        }
        __syncthreads();

        // ---- S = Q @ K^T (bf16x3), warp tile 16 x 128 ----
        float sacc[16][4];
        #pragma unroll
        for (int nt = 0; nt < 16; nt++)
            #pragma unroll
            for (int q = 0; q < 4; q++) sacc[nt][q] = 0.0f;

        #pragma unroll
        for (int kk = 0; kk < 4; kk++) {
            uint32_t aqh[4], aql[4];
            ldm_x4(aqh, qa + kk * 32);
            ldm_x4(aql, qa + QLO + kk * 32);
            #pragma unroll
            for (int p = 0; p < 8; p++) {
                uint32_t kh[4], kl[4];
                ldm_x4(kh, ka + p * (16 * KSTR) + kk * 32);
                ldm_x4(kl, ka + KLO + p * (16 * KSTR) + kk * 32);
                uint32_t b0h[2] = { kh[0], kh[2] };
                uint32_t b1h[2] = { kh[1], kh[3] };
                uint32_t b0l[2] = { kl[0], kl[2] };
                uint32_t b1l[2] = { kl[1], kl[3] };
                mma16816(sacc[2*p+0], aqh, b0h);
                mma16816(sacc[2*p+1], aqh, b1h);
                mma16816(sacc[2*p+0], aqh, b0l);
                mma16816(sacc[2*p+1], aqh, b1l);
                mma16816(sacc[2*p+0], aql, b0h);
                mma16816(sacc[2*p+1], aql, b1h);
            }
        }

        // ---- online softmax (warp-local) ----
        float mx0 = -1e30f, mx1 = -1e30f;
        #pragma unroll
        for (int nt = 0; nt < 16; nt++) {
            mx0 = fmaxf(mx0, fmaxf(sacc[nt][0], sacc[nt][1]));
            mx1 = fmaxf(mx1, fmaxf(sacc[nt][2], sacc[nt][3]));
        }
        mx0 = fmaxf(mx0, __shfl_xor_sync(0xffffffffu, mx0, 1));
        mx0 = fmaxf(mx0, __shfl_xor_sync(0xffffffffu, mx0, 2));
        mx1 = fmaxf(mx1, __shfl_xor_sync(0xffffffffu, mx1, 1));
        mx1 = fmaxf(mx1, __shfl_xor_sync(0xffffffffu, mx1, 2));
        float mn0 = fmaxf(m0, mx0), mn1 = fmaxf(m1, mx1);
        float a0 = __expf(m0 - mn0), a1 = __expf(m1 - mn1);
        m0 = mn0; m1 = mn1;

        float ls0 = 0.0f, ls1 = 0.0f;
        #pragma unroll
        for (int nt = 0; nt < 16; nt++) {
            sacc[nt][0] = __expf(sacc[nt][0] - mn0);
            sacc[nt][1] = __expf(sacc[nt][1] - mn0);
            sacc[nt][2] = __expf(sacc[nt][2] - mn1);
            sacc[nt][3] = __expf(sacc[nt][3] - mn1);
            ls0 += sacc[nt][0] + sacc[nt][1];
            ls1 += sacc[nt][2] + sacc[nt][3];
        }
        l0 = l0 * a0 + ls0;
        l1 = l1 * a1 + ls1;
        #pragma unroll
        for (int nt = 0; nt < 8; nt++) {
            oacc[nt][0] *= a0; oacc[nt][1] *= a0;
            oacc[nt][2] *= a1; oacc[nt][3] *= a1;
        }

        // ---- O += P @ V (bf16x3); P frags straight from sacc registers ----
        #pragma unroll
        for (int kk = 0; kk < 8; kk++) {
            uint32_t ph[4], pl[4];
            split2(sacc[2*kk  ][0], sacc[2*kk  ][1], ph[0], pl[0]);
            split2(sacc[2*kk  ][2], sacc[2*kk  ][3], ph[1], pl[1]);
            split2(sacc[2*kk+1][0], sacc[2*kk+1][1], ph[2], pl[2]);
            split2(sacc[2*kk+1][2], sacc[2*kk+1][3], ph[3], pl[3]);
            #pragma unroll
            for (int nd = 0; nd < 4; nd++) {
                uint32_t vh[4], vl[4];
                ldm_x4(vh, va + nd * (16 * VSTR) + kk * 32);
                ldm_x4(vl, va + VLO + nd * (16 * VSTR) + kk * 32);
                uint32_t b0h[2] = { vh[0], vh[2] };
                uint32_t b1h[2] = { vh[1], vh[3] };
                uint32_t b0l[2] = { vl[0], vl[2] };
                uint32_t b1l[2] = { vl[1], vl[3] };
                mma16816(oacc[2*nd+0], ph, b0h);
                mma16816(oacc[2*nd+1], ph, b1h);
                mma16816(oacc[2*nd+0], ph, b0l);
                mma16816(oacc[2*nd+1], ph, b1l);
                mma16816(oacc[2*nd+0], pl, b0h);
                mma16816(oacc[2*nd+1], pl, b1h);
            }
        }
    }

    // ---- finalize: reduce l over t-lanes, normalize, store ----
    l0 += __shfl_xor_sync(0xffffffffu, l0, 1);
    l0 += __shfl_xor_sync(0xffffffffu, l0, 2);
    l1 += __shfl_xor_sync(0xffffffffu, l1, 1);
    l1 += __shfl_xor_sync(0xffffffffu, l1, 2);
    float inv0 = 1.0f / l0, inv1 = 1.0f / l1;

    const int g = lane >> 2, t = lane & 3;
    const int row = q0 + wid * 16 + g;
    float* o0 = att + (size_t)(b * SEQ + row) * EMB + h * HD;
    float* o1 = att + (size_t)(b * SEQ + row + 8) * EMB + h * HD;
    #pragma unroll
    for (int nt = 0; nt < 8; nt++) {
        int col = nt * 8 + t * 2;
        *(float2*)(o0 + col) = make_float2(oacc[nt][0] * inv0, oacc[nt][1] * inv0);
        *(float2*)(o1 + col) = make_float2(oacc[nt][2] * inv1, oacc[nt][3] * inv1);
    }
}

// ---------------------------------------------------------------------------
extern "C" void kernel_launch(void* const* d_in, const int* in_sizes, int n_in,
                              void* d_out, int out_size)
{
    const float* x      = (const float*)d_in[0];
    const float* w_qkv  = (const float*)d_in[1];
    const float* b_qkv  = (const float*)d_in[2];
    const float* w_proj = (const float*)d_in[3];
    const float* b_proj = (const float*)d_in[4];
    float* out = (float*)d_out;

    float* qkv_ptr = nullptr;
    float* att_ptr = nullptr;
    cudaGetSymbolAddress((void**)&qkv_ptr, g_qkv);
    cudaGetSymbolAddress((void**)&att_ptr, g_att);

    cudaFuncSetAttribute(gemm_hmma, cudaFuncAttributeMaxDynamicSharedMemorySize, GEMM_SMEM);
    cudaFuncSetAttribute(attn_hmma, cudaFuncAttributeMaxDynamicSharedMemorySize, ATT_SMEM);

    // 1) QKV projection
    dim3 g1(3 * EMB / 128, TOK / 128);
    gemm_hmma<<<g1, 256, GEMM_SMEM>>>(x, w_qkv, b_qkv, qkv_ptr, TOK, 3 * EMB, EMB);

    // 2) Attention
    dim3 g2(SEQ / 128, BATCH * NH);
    attn_hmma<<<g2, 256, ATT_SMEM>>>(qkv_ptr, att_ptr);

    // 3) Output projection
    dim3 g3(EMB / 128, TOK / 128);
    gemm_hmma<<<g3, 256, GEMM_SMEM>>>(att_ptr, w_proj, b_proj, out, TOK, EMB, EMB);
}

// round 5
// speedup vs baseline: 2.4866x; 1.1636x over previous
#include <cuda_runtime.h>
#include <cuda_bf16.h>
#include <cstdint>

#define BATCH 4
#define SEQ   2048
#define EMB   1024
#define NH    16
#define HD    64
#define TOK   (BATCH*SEQ)      // 8192

// ---------------- scratch (device globals; allocation-free rule) ----------
__device__ __nv_bfloat16 g_xh[(size_t)TOK * EMB];
__device__ __nv_bfloat16 g_xl[(size_t)TOK * EMB];
__device__ __nv_bfloat16 g_wqh[(size_t)3 * EMB * EMB];
__device__ __nv_bfloat16 g_wql[(size_t)3 * EMB * EMB];
__device__ __nv_bfloat16 g_wph[(size_t)EMB * EMB];
__device__ __nv_bfloat16 g_wpl[(size_t)EMB * EMB];
__device__ __nv_bfloat16 g_qkvh[(size_t)TOK * 3 * EMB];
__device__ __nv_bfloat16 g_qkvl[(size_t)TOK * 3 * EMB];
__device__ __nv_bfloat16 g_atth[(size_t)TOK * EMB];
__device__ __nv_bfloat16 g_attl[(size_t)TOK * EMB];

// ---------------- primitives ----------------
__device__ __forceinline__ uint32_t smem_u32(const void* p) {
    uint32_t a;
    asm("{ .reg .u64 t; cvta.to.shared.u64 t, %1; cvt.u32.u64 %0, t; }" : "=r"(a) : "l"(p));
    return a;
}
__device__ __forceinline__ void ldm_x4(uint32_t* r, uint32_t addr) {
    asm volatile("ldmatrix.sync.aligned.m8n8.x4.shared.b16 {%0,%1,%2,%3}, [%4];"
        : "=r"(r[0]), "=r"(r[1]), "=r"(r[2]), "=r"(r[3]) : "r"(addr));
}
__device__ __forceinline__ void ldm_x4_t(uint32_t* r, uint32_t addr) {
    asm volatile("ldmatrix.sync.aligned.m8n8.x4.trans.shared.b16 {%0,%1,%2,%3}, [%4];"
        : "=r"(r[0]), "=r"(r[1]), "=r"(r[2]), "=r"(r[3]) : "r"(addr));
}
__device__ __forceinline__ void mma16816(float* c, const uint32_t* a, const uint32_t* b) {
    asm volatile(
        "mma.sync.aligned.m16n8k16.row.col.f32.bf16.bf16.f32 "
        "{%0,%1,%2,%3}, {%4,%5,%6,%7}, {%8,%9}, {%0,%1,%2,%3};"
        : "+f"(c[0]), "+f"(c[1]), "+f"(c[2]), "+f"(c[3])
        : "r"(a[0]), "r"(a[1]), "r"(a[2]), "r"(a[3]), "r"(b[0]), "r"(b[1]));
}
#define CP16(dst, src) \
    asm volatile("cp.async.cg.shared.global [%0], [%1], 16;" \
        :: "r"(dst), "l"(src) : "memory")

__device__ __forceinline__ void cvt_split(float4 v, uint2& hi, uint2& lo) {
    __nv_bfloat162 h0 = __floats2bfloat162_rn(v.x, v.y);
    __nv_bfloat162 h1 = __floats2bfloat162_rn(v.z, v.w);
    float rx = __bfloat162float(h0.x), ry = __bfloat162float(h0.y);
    float rz = __bfloat162float(h1.x), rw = __bfloat162float(h1.y);
    __nv_bfloat162 l0 = __floats2bfloat162_rn(v.x - rx, v.y - ry);
    __nv_bfloat162 l1 = __floats2bfloat162_rn(v.z - rz, v.w - rw);
    hi.x = *(uint32_t*)&h0; hi.y = *(uint32_t*)&h1;
    lo.x = *(uint32_t*)&l0; lo.y = *(uint32_t*)&l1;
}
__device__ __forceinline__ void split2(float x, float y, uint32_t& h, uint32_t& l) {
    __nv_bfloat162 hh = __floats2bfloat162_rn(x, y);
    h = *(uint32_t*)&hh;
    __nv_bfloat162 ll = __floats2bfloat162_rn(x - __bfloat162float(hh.x),
                                              y - __bfloat162float(hh.y));
    l = *(uint32_t*)&ll;
}

// ---------------- fp32 -> split bf16 planes ----------------
__global__ void __launch_bounds__(256)
split_f32(const float* __restrict__ in, __nv_bfloat16* __restrict__ h,
          __nv_bfloat16* __restrict__ l, int n4)
{
    int i = blockIdx.x * blockDim.x + threadIdx.x;
    if (i < n4) {
        float4 v = ((const float4*)in)[i];
        uint2 hi, lo;
        cvt_split(v, hi, lo);
        ((uint2*)h)[i] = hi;
        ((uint2*)l)[i] = lo;
    }
}

// ================= pre-split GEMM, cp.async pipelined =================
// C[m,n] = sum_k A[m,k]*W[n,k] + bias[n]; A,W pre-split bf16 hi/lo, K-major.
#define ROWB    80
#define PLANE_B (128 * ROWB)      // 10240
#define BUF_B   (4 * PLANE_B)     // 40960
#define PIPE    3
#define GEMM_SMEM (PIPE * BUF_B)  // 122880

template<bool SPLIT_OUT>
__global__ void __launch_bounds__(256)
gemm_pre(const __nv_bfloat16* __restrict__ Ah, const __nv_bfloat16* __restrict__ Al,
         const __nv_bfloat16* __restrict__ Wh, const __nv_bfloat16* __restrict__ Wl,
         const float* __restrict__ bias,
         float* __restrict__ Cf,
         __nv_bfloat16* __restrict__ Ch, __nv_bfloat16* __restrict__ Cl,
         int M, int N, int K, int qcols, float qscale)
{
    extern __shared__ __align__(128) char smem[];
    const uint32_t sb = smem_u32(smem);
    const int tid = threadIdx.x;
    const int lane = tid & 31, wid = tid >> 5;
    const int wm = wid >> 1, wn = wid & 1;
    const int m0 = blockIdx.y * 128;
    const int n0 = blockIdx.x * 128;

    float acc[2][8][4] = {};

    const int frow = lane & 15;
    const int fcol = ((lane >> 4) & 1) * 16;
    uint32_t a_addr[2], b_addr[4];
    #pragma unroll
    for (int mt = 0; mt < 2; mt++)
        a_addr[mt] = (uint32_t)((wm * 32 + mt * 16 + frow) * ROWB + fcol);
    #pragma unroll
    for (int p = 0; p < 4; p++)
        b_addr[p] = (uint32_t)((wn * 64 + p * 16 + frow) * ROWB + fcol);

    auto issue = [&](int stage, int k0) {
        const uint32_t sbuf = sb + stage * BUF_B;
        #pragma unroll
        for (int j = 0; j < 2; j++) {
            int cid = tid + j * 256;            // 0..511
            int r = cid >> 2, c16 = cid & 3;
            uint32_t so = (uint32_t)(r * ROWB + c16 * 16);
            size_t ga = (size_t)(m0 + r) * K + k0 + c16 * 8;
            size_t gb = (size_t)(n0 + r) * K + k0 + c16 * 8;
            CP16(sbuf + 0 * PLANE_B + so, Ah + ga);
            CP16(sbuf + 1 * PLANE_B + so, Al + ga);
            CP16(sbuf + 2 * PLANE_B + so, Wh + gb);
            CP16(sbuf + 3 * PLANE_B + so, Wl + gb);
        }
        asm volatile("cp.async.commit_group;" ::: "memory");
    };

    const int nch = K / 32;
    issue(0, 0);
    issue(1, 32);

    for (int i = 0; i < nch; i++) {
        asm volatile("cp.async.wait_group 1;" ::: "memory");
        __syncthreads();
        if (i + 2 < nch) issue((i + 2) % PIPE, (i + 2) * 32);
        else asm volatile("cp.async.commit_group;" ::: "memory");

        const uint32_t base = sb + (i % PIPE) * BUF_B;
        #pragma unroll
        for (int kh = 0; kh < 2; kh++) {
            const uint32_t kb = kh * 32;
            uint32_t ah[2][4], av[2][4], bh[4][4], bl[4][4];
            #pragma unroll
            for (int mt = 0; mt < 2; mt++) {
                ldm_x4(ah[mt], base + 0 * PLANE_B + a_addr[mt] + kb);
                ldm_x4(av[mt], base + 1 * PLANE_B + a_addr[mt] + kb);
            }
            #pragma unroll
            for (int p = 0; p < 4; p++) {
                ldm_x4(bh[p], base + 2 * PLANE_B + b_addr[p] + kb);
                ldm_x4(bl[p], base + 3 * PLANE_B + b_addr[p] + kb);
            }
            #pragma unroll
            for (int mt = 0; mt < 2; mt++) {
                #pragma unroll
                for (int p = 0; p < 4; p++) {
                    uint32_t b0h[2] = { bh[p][0], bh[p][2] };
                    uint32_t b1h[2] = { bh[p][1], bh[p][3] };
                    uint32_t b0l[2] = { bl[p][0], bl[p][2] };
                    uint32_t b1l[2] = { bl[p][1], bl[p][3] };
                    mma16816(acc[mt][2*p+0], ah[mt], b0h);
                    mma16816(acc[mt][2*p+1], ah[mt], b1h);
                    mma16816(acc[mt][2*p+0], ah[mt], b0l);
                    mma16816(acc[mt][2*p+1], ah[mt], b1l);
                    mma16816(acc[mt][2*p+0], av[mt], b0h);
                    mma16816(acc[mt][2*p+1], av[mt], b1h);
                }
            }
        }
    }

    // epilogue
    const int g = lane >> 2, t = lane & 3;
    #pragma unroll
    for (int mt = 0; mt < 2; mt++) {
        int row = m0 + wm * 32 + mt * 16 + g;
        #pragma unroll
        for (int nt = 0; nt < 8; nt++) {
            int col = n0 + wn * 64 + nt * 8 + t * 2;
            float bx = bias[col], by = bias[col + 1];
            float* c = acc[mt][nt];
            float v0 = c[0] + bx, v1 = c[1] + by;
            float v2 = c[2] + bx, v3 = c[3] + by;
            if (SPLIT_OUT) {
                float s = (col < qcols) ? qscale : 1.0f;
                uint32_t h0, l0, h1, l1;
                split2(v0 * s, v1 * s, h0, l0);
                split2(v2 * s, v3 * s, h1, l1);
                *(uint32_t*)&Ch[(size_t)row * N + col] = h0;
                *(uint32_t*)&Cl[(size_t)row * N + col] = l0;
                *(uint32_t*)&Ch[(size_t)(row + 8) * N + col] = h1;
                *(uint32_t*)&Cl[(size_t)(row + 8) * N + col] = l1;
            } else {
                *(float2*)(Cf + (size_t)row * N + col) = make_float2(v0, v1);
                *(float2*)(Cf + (size_t)(row + 8) * N + col) = make_float2(v2, v3);
            }
        }
    }
}

// ================= HMMA flash attention (pre-split bf16 I/O) =================
// CTA = 128 queries of one (b,h); 16 key tiles of 128. 8 warps, warp-local softmax.
// Q/K smem [row][d] hi/lo; V smem [key][d] hi/lo fed via ldmatrix.trans.
// Q pre-scaled by 0.125*log2(e) (folded into QKV GEMM) -> base-2 softmax.
#define KSTR 144
#define AQH 0
#define AQL (1 * 128 * KSTR)
#define AKH (2 * 128 * KSTR)
#define AKL (3 * 128 * KSTR)
#define AVH (4 * 128 * KSTR)
#define AVL (5 * 128 * KSTR)
#define ATT_SMEM (6 * 128 * KSTR)   // 110592

__global__ void __launch_bounds__(256)
attn_pre(const __nv_bfloat16* __restrict__ qkvh,
         const __nv_bfloat16* __restrict__ qkvl,
         __nv_bfloat16* __restrict__ atth,
         __nv_bfloat16* __restrict__ attl)
{
    extern __shared__ __align__(128) char smem[];
    const uint32_t sb = smem_u32(smem);
    const int tid = threadIdx.x;
    const int lane = tid & 31, wid = tid >> 5;
    const int b = blockIdx.y >> 4, h = blockIdx.y & 15;
    const int q0 = blockIdx.x * 128;

    const size_t rs = 3 * EMB;
    const __nv_bfloat16* Qh = qkvh + (size_t)(b * SEQ) * rs + h * HD;
    const __nv_bfloat16* Ql = qkvl + (size_t)(b * SEQ) * rs + h * HD;
    const __nv_bfloat16* Kh = Qh + EMB;
    const __nv_bfloat16* Kl = Ql + EMB;
    const __nv_bfloat16* Vh = Qh + 2 * EMB;
    const __nv_bfloat16* Vl = Ql + 2 * EMB;

    // ---- load Q tile (plain 16B copies; already scaled & split) ----
    #pragma unroll
    for (int i = 0; i < 4; i++) {
        int idx = tid + i * 256;           // 0..1023
        int r = idx >> 3, c16 = idx & 7;
        size_t go = (size_t)(q0 + r) * rs + c16 * 8;
        uint32_t so = r * KSTR + c16 * 16;
        *(uint4*)(smem + AQH + so) = *(const uint4*)(Qh + go);
        *(uint4*)(smem + AQL + so) = *(const uint4*)(Ql + go);
    }

    const int frow = lane & 15;
    const int fcol = ((lane >> 4) & 1) * 16;
    const uint32_t qa = sb + AQH + (uint32_t)((wid * 16 + frow) * KSTR + fcol);
    const uint32_t ka = sb + AKH + (uint32_t)(frow * KSTR + fcol);
    const uint32_t va = sb + AVH + (uint32_t)(frow * KSTR + fcol);
    const uint32_t QLO = AQL - AQH;
    const uint32_t KLO = AKL - AKH;
    const uint32_t VLO = AVL - AVH;

    float oacc[8][4] = {};
    float m0 = -1e30f, m1 = -1e30f;
    float l0 = 0.0f, l1 = 0.0f;

    for (int kt = 0; kt < SEQ / 128; kt++) {
        const int k0 = kt * 128;
        __syncthreads();

        // ---- load K and V tiles (16B copies, no conversion) ----
        #pragma unroll
        for (int i = 0; i < 4; i++) {
            int idx = tid + i * 256;
            int r = idx >> 3, c16 = idx & 7;
            size_t go = (size_t)(k0 + r) * rs + c16 * 8;
            uint32_t so = r * KSTR + c16 * 16;
            *(uint4*)(smem + AKH + so) = *(const uint4*)(Kh + go);
            *(uint4*)(smem + AKL + so) = *(const uint4*)(Kl + go);
            *(uint4*)(smem + AVH + so) = *(const uint4*)(Vh + go);
            *(uint4*)(smem + AVL + so) = *(const uint4*)(Vl + go);
        }
        __syncthreads();

        // ---- S = Q @ K^T (bf16x3), warp tile 16 x 128 ----
        float sacc[16][4] = {};
        #pragma unroll
        for (int kk = 0; kk < 4; kk++) {
            uint32_t aqh[4], aql[4];
            ldm_x4(aqh, qa + kk * 32);
            ldm_x4(aql, qa + QLO + kk * 32);
            #pragma unroll
            for (int p = 0; p < 8; p++) {
                uint32_t kh[4], kl[4];
                ldm_x4(kh, ka + p * (16 * KSTR) + kk * 32);
                ldm_x4(kl, ka + KLO + p * (16 * KSTR) + kk * 32);
                uint32_t b0h[2] = { kh[0], kh[2] };
                uint32_t b1h[2] = { kh[1], kh[3] };
                uint32_t b0l[2] = { kl[0], kl[2] };
                uint32_t b1l[2] = { kl[1], kl[3] };
                mma16816(sacc[2*p+0], aqh, b0h);
                mma16816(sacc[2*p+1], aqh, b1h);
                mma16816(sacc[2*p+0], aqh, b0l);
                mma16816(sacc[2*p+1], aqh, b1l);
                mma16816(sacc[2*p+0], aql, b0h);
                mma16816(sacc[2*p+1], aql, b1h);
            }
        }

        // ---- online softmax (base-2, warp-local) ----
        float mx0 = -1e30f, mx1 = -1e30f;
        #pragma unroll
        for (int nt = 0; nt < 16; nt++) {
            mx0 = fmaxf(mx0, fmaxf(sacc[nt][0], sacc[nt][1]));
            mx1 = fmaxf(mx1, fmaxf(sacc[nt][2], sacc[nt][3]));
        }
        mx0 = fmaxf(mx0, __shfl_xor_sync(0xffffffffu, mx0, 1));
        mx0 = fmaxf(mx0, __shfl_xor_sync(0xffffffffu, mx0, 2));
        mx1 = fmaxf(mx1, __shfl_xor_sync(0xffffffffu, mx1, 1));
        mx1 = fmaxf(mx1, __shfl_xor_sync(0xffffffffu, mx1, 2));
        float mn0 = fmaxf(m0, mx0), mn1 = fmaxf(m1, mx1);
        float a0 = exp2f(m0 - mn0), a1 = exp2f(m1 - mn1);
        m0 = mn0; m1 = mn1;

        float ls0 = 0.0f, ls1 = 0.0f;
        #pragma unroll
        for (int nt = 0; nt < 16; nt++) {
            sacc[nt][0] = exp2f(sacc[nt][0] - mn0);
            sacc[nt][1] = exp2f(sacc[nt][1] - mn0);
            sacc[nt][2] = exp2f(sacc[nt][2] - mn1);
            sacc[nt][3] = exp2f(sacc[nt][3] - mn1);
            ls0 += sacc[nt][0] + sacc[nt][1];
            ls1 += sacc[nt][2] + sacc[nt][3];
        }
        l0 = l0 * a0 + ls0;
        l1 = l1 * a1 + ls1;
        #pragma unroll
        for (int nt = 0; nt < 8; nt++) {
            oacc[nt][0] *= a0; oacc[nt][1] *= a0;
            oacc[nt][2] *= a1; oacc[nt][3] *= a1;
        }

        // ---- O += P @ V (bf16x3); V via ldmatrix.trans ----
        #pragma unroll
        for (int kk = 0; kk < 8; kk++) {
            uint32_t ph[4], pl[4];
            split2(sacc[2*kk  ][0], sacc[2*kk  ][1], ph[0], pl[0]);
            split2(sacc[2*kk  ][2], sacc[2*kk  ][3], ph[1], pl[1]);
            split2(sacc[2*kk+1][0], sacc[2*kk+1][1], ph[2], pl[2]);
            split2(sacc[2*kk+1][2], sacc[2*kk+1][3], ph[3], pl[3]);
            #pragma unroll
            for (int nd = 0; nd < 4; nd++) {
                uint32_t vh[4], vl[4];
                ldm_x4_t(vh, va + kk * (16 * KSTR) + nd * 32);
                ldm_x4_t(vl, va + VLO + kk * (16 * KSTR) + nd * 32);
                uint32_t b0h[2] = { vh[0], vh[1] };
                uint32_t b1h[2] = { vh[2], vh[3] };
                uint32_t b0l[2] = { vl[0], vl[1] };
                uint32_t b1l[2] = { vl[2], vl[3] };
                mma16816(oacc[2*nd+0], ph, b0h);
                mma16816(oacc[2*nd+1], ph, b1h);
                mma16816(oacc[2*nd+0], ph, b0l);
                mma16816(oacc[2*nd+1], ph, b1l);
                mma16816(oacc[2*nd+0], pl, b0h);
                mma16816(oacc[2*nd+1], pl, b1h);
            }
        }
    }

    // ---- finalize: reduce l, normalize, split-store bf16 ----
    l0 += __shfl_xor_sync(0xffffffffu, l0, 1);
    l0 += __shfl_xor_sync(0xffffffffu, l0, 2);
    l1 += __shfl_xor_sync(0xffffffffu, l1, 1);
    l1 += __shfl_xor_sync(0xffffffffu, l1, 2);
    float inv0 = 1.0f / l0, inv1 = 1.0f / l1;

    const int g = lane >> 2, t = lane & 3;
    const int row = q0 + wid * 16 + g;
    size_t o0 = (size_t)(b * SEQ + row) * EMB + h * HD;
    size_t o1 = (size_t)(b * SEQ + row + 8) * EMB + h * HD;
    #pragma unroll
    for (int nt = 0; nt < 8; nt++) {
        int col = nt * 8 + t * 2;
        uint32_t h0, lo0, h1, lo1;
        split2(oacc[nt][0] * inv0, oacc[nt][1] * inv0, h0, lo0);
        split2(oacc[nt][2] * inv1, oacc[nt][3] * inv1, h1, lo1);
        *(uint32_t*)&atth[o0 + col] = h0;
        *(uint32_t*)&attl[o0 + col] = lo0;
        *(uint32_t*)&atth[o1 + col] = h1;
        *(uint32_t*)&attl[o1 + col] = lo1;
    }
}

// ---------------------------------------------------------------------------
extern "C" void kernel_launch(void* const* d_in, const int* in_sizes, int n_in,
                              void* d_out, int out_size)
{
    const float* x      = (const float*)d_in[0];
    const float* w_qkv  = (const float*)d_in[1];
    const float* b_qkv  = (const float*)d_in[2];
    const float* w_proj = (const float*)d_in[3];
    const float* b_proj = (const float*)d_in[4];
    float* out = (float*)d_out;

    __nv_bfloat16 *xh, *xl, *wqh, *wql, *wph, *wpl, *qh, *ql, *ath, *atl;
    cudaGetSymbolAddress((void**)&xh, g_xh);
    cudaGetSymbolAddress((void**)&xl, g_xl);
    cudaGetSymbolAddress((void**)&wqh, g_wqh);
    cudaGetSymbolAddress((void**)&wql, g_wql);
    cudaGetSymbolAddress((void**)&wph, g_wph);
    cudaGetSymbolAddress((void**)&wpl, g_wpl);
    cudaGetSymbolAddress((void**)&qh, g_qkvh);
    cudaGetSymbolAddress((void**)&ql, g_qkvl);
    cudaGetSymbolAddress((void**)&ath, g_atth);
    cudaGetSymbolAddress((void**)&atl, g_attl);

    cudaFuncSetAttribute(gemm_pre<true>,  cudaFuncAttributeMaxDynamicSharedMemorySize, GEMM_SMEM);
    cudaFuncSetAttribute(gemm_pre<false>, cudaFuncAttributeMaxDynamicSharedMemorySize, GEMM_SMEM);
    cudaFuncSetAttribute(attn_pre, cudaFuncAttributeMaxDynamicSharedMemorySize, ATT_SMEM);

    // 0) pre-split operands
    {
        int n4 = TOK * EMB / 4;
        split_f32<<<(n4 + 255) / 256, 256>>>(x, xh, xl, n4);
        n4 = 3 * EMB * EMB / 4;
        split_f32<<<(n4 + 255) / 256, 256>>>(w_qkv, wqh, wql, n4);
        n4 = EMB * EMB / 4;
        split_f32<<<(n4 + 255) / 256, 256>>>(w_proj, wph, wpl, n4);
    }

    const float QSCALE = 0.125f * 1.4426950408889634f;   // 1/sqrt(64) * log2(e)

    // 1) QKV projection -> split bf16 qkv (Q columns pre-scaled)
    dim3 g1(3 * EMB / 128, TOK / 128);
    gemm_pre<true><<<g1, 256, GEMM_SMEM>>>(xh, xl, wqh, wql, b_qkv,
                                           nullptr, qh, ql,
                                           TOK, 3 * EMB, EMB, EMB, QSCALE);

    // 2) Attention -> split bf16 att
    dim3 g2(SEQ / 128, BATCH * NH);
    attn_pre<<<g2, 256, ATT_SMEM>>>(qh, ql, ath, atl);

    // 3) Output projection -> fp32 out
    dim3 g3(EMB / 128, TOK / 128);
    gemm_pre<false><<<g3, 256, GEMM_SMEM>>>(ath, atl, wph, wpl, b_proj,
                                            out, nullptr, nullptr,
                                            TOK, EMB, EMB, 0, 1.0f);
}

// round 6
// speedup vs baseline: 2.6707x; 1.0740x over previous
#include <cuda_runtime.h>
#include <cuda_bf16.h>
#include <cstdint>

#define BATCH 4
#define SEQ   2048
#define EMB   1024
#define NH    16
#define HD    64
#define TOK   (BATCH*SEQ)      // 8192

// ---------------- scratch (device globals; allocation-free rule) ----------
__device__ __nv_bfloat16 g_xh[(size_t)TOK * EMB];
__device__ __nv_bfloat16 g_xl[(size_t)TOK * EMB];
__device__ __nv_bfloat16 g_wqh[(size_t)3 * EMB * EMB];
__device__ __nv_bfloat16 g_wql[(size_t)3 * EMB * EMB];
__device__ __nv_bfloat16 g_wph[(size_t)EMB * EMB];
__device__ __nv_bfloat16 g_wpl[(size_t)EMB * EMB];
__device__ __nv_bfloat16 g_qkvh[(size_t)TOK * 3 * EMB];
__device__ __nv_bfloat16 g_qkvl[(size_t)TOK * 3 * EMB];
__device__ __nv_bfloat16 g_atth[(size_t)TOK * EMB];
__device__ __nv_bfloat16 g_attl[(size_t)TOK * EMB];

// ---------------- primitives ----------------
__device__ __forceinline__ uint32_t smem_u32(const void* p) {
    uint32_t a;
    asm("{ .reg .u64 t; cvta.to.shared.u64 t, %1; cvt.u32.u64 %0, t; }" : "=r"(a) : "l"(p));
    return a;
}
__device__ __forceinline__ void ldm_x4(uint32_t* r, uint32_t addr) {
    asm volatile("ldmatrix.sync.aligned.m8n8.x4.shared.b16 {%0,%1,%2,%3}, [%4];"
        : "=r"(r[0]), "=r"(r[1]), "=r"(r[2]), "=r"(r[3]) : "r"(addr));
}
__device__ __forceinline__ void ldm_x4_t(uint32_t* r, uint32_t addr) {
    asm volatile("ldmatrix.sync.aligned.m8n8.x4.trans.shared.b16 {%0,%1,%2,%3}, [%4];"
        : "=r"(r[0]), "=r"(r[1]), "=r"(r[2]), "=r"(r[3]) : "r"(addr));
}
__device__ __forceinline__ void mma16816(float* c, const uint32_t* a, const uint32_t* b) {
    asm volatile(
        "mma.sync.aligned.m16n8k16.row.col.f32.bf16.bf16.f32 "
        "{%0,%1,%2,%3}, {%4,%5,%6,%7}, {%8,%9}, {%0,%1,%2,%3};"
        : "+f"(c[0]), "+f"(c[1]), "+f"(c[2]), "+f"(c[3])
        : "r"(a[0]), "r"(a[1]), "r"(a[2]), "r"(a[3]), "r"(b[0]), "r"(b[1]));
}
#define CP16(dst, src) \
    asm volatile("cp.async.cg.shared.global [%0], [%1], 16;" \
        :: "r"(dst), "l"(src) : "memory")

__device__ __forceinline__ void cvt_split(float4 v, uint2& hi, uint2& lo) {
    __nv_bfloat162 h0 = __floats2bfloat162_rn(v.x, v.y);
    __nv_bfloat162 h1 = __floats2bfloat162_rn(v.z, v.w);
    float rx = __bfloat162float(h0.x), ry = __bfloat162float(h0.y);
    float rz = __bfloat162float(h1.x), rw = __bfloat162float(h1.y);
    __nv_bfloat162 l0 = __floats2bfloat162_rn(v.x - rx, v.y - ry);
    __nv_bfloat162 l1 = __floats2bfloat162_rn(v.z - rz, v.w - rw);
    hi.x = *(uint32_t*)&h0; hi.y = *(uint32_t*)&h1;
    lo.x = *(uint32_t*)&l0; lo.y = *(uint32_t*)&l1;
}
__device__ __forceinline__ void split2(float x, float y, uint32_t& h, uint32_t& l) {
    __nv_bfloat162 hh = __floats2bfloat162_rn(x, y);
    h = *(uint32_t*)&hh;
    __nv_bfloat162 ll = __floats2bfloat162_rn(x - __bfloat162float(hh.x),
                                              y - __bfloat162float(hh.y));
    l = *(uint32_t*)&ll;
}

// ---------------- fp32 -> split bf16 planes ----------------
__global__ void __launch_bounds__(256)
split_f32(const float* __restrict__ in, __nv_bfloat16* __restrict__ h,
          __nv_bfloat16* __restrict__ l, int n4)
{
    int i = blockIdx.x * blockDim.x + threadIdx.x;
    if (i < n4) {
        float4 v = ((const float4*)in)[i];
        uint2 hi, lo;
        cvt_split(v, hi, lo);
        ((uint2*)h)[i] = hi;
        ((uint2*)l)[i] = lo;
    }
}

// ================= pre-split GEMM, cp.async, 2 CTAs/SM =================
#define ROWB    80
#define PLANE_B (128 * ROWB)      // 10240
#define BUF_B   (4 * PLANE_B)     // 40960
#define GEMM_SMEM (2 * BUF_B)     // 81920 -> 2 CTAs/SM

template<bool SPLIT_OUT>
__global__ void __launch_bounds__(256, 2)
gemm_pre(const __nv_bfloat16* __restrict__ Ah, const __nv_bfloat16* __restrict__ Al,
         const __nv_bfloat16* __restrict__ Wh, const __nv_bfloat16* __restrict__ Wl,
         const float* __restrict__ bias,
         float* __restrict__ Cf,
         __nv_bfloat16* __restrict__ Ch, __nv_bfloat16* __restrict__ Cl,
         int M, int N, int K, int qcols, float qscale)
{
    extern __shared__ __align__(128) char smem[];
    const uint32_t sb = smem_u32(smem);
    const int tid = threadIdx.x;
    const int lane = tid & 31, wid = tid >> 5;
    const int wm = wid >> 1, wn = wid & 1;
    const int m0 = blockIdx.y * 128;
    const int n0 = blockIdx.x * 128;

    float acc[2][8][4] = {};

    const int frow = lane & 15;
    const int fcol = ((lane >> 4) & 1) * 16;
    uint32_t a_addr[2], b_addr[4];
    #pragma unroll
    for (int mt = 0; mt < 2; mt++)
        a_addr[mt] = (uint32_t)((wm * 32 + mt * 16 + frow) * ROWB + fcol);
    #pragma unroll
    for (int p = 0; p < 4; p++)
        b_addr[p] = (uint32_t)((wn * 64 + p * 16 + frow) * ROWB + fcol);

    auto issue = [&](int stage, int k0) {
        const uint32_t sbuf = sb + stage * BUF_B;
        #pragma unroll
        for (int j = 0; j < 2; j++) {
            int cid = tid + j * 256;
            int r = cid >> 2, c16 = cid & 3;
            uint32_t so = (uint32_t)(r * ROWB + c16 * 16);
            size_t ga = (size_t)(m0 + r) * K + k0 + c16 * 8;
            size_t gb = (size_t)(n0 + r) * K + k0 + c16 * 8;
            CP16(sbuf + 0 * PLANE_B + so, Ah + ga);
            CP16(sbuf + 1 * PLANE_B + so, Al + ga);
            CP16(sbuf + 2 * PLANE_B + so, Wh + gb);
            CP16(sbuf + 3 * PLANE_B + so, Wl + gb);
        }
        asm volatile("cp.async.commit_group;" ::: "memory");
    };

    const int nch = K / 32;
    issue(0, 0);

    for (int i = 0; i < nch; i++) {
        if (i + 1 < nch) issue((i + 1) & 1, (i + 1) * 32);
        else asm volatile("cp.async.commit_group;" ::: "memory");
        asm volatile("cp.async.wait_group 1;" ::: "memory");
        __syncthreads();

        const uint32_t base = sb + (i & 1) * BUF_B;
        #pragma unroll
        for (int kh = 0; kh < 2; kh++) {
            const uint32_t kb = kh * 32;
            uint32_t ah[2][4], av[2][4], bh[4][4], bl[4][4];
            #pragma unroll
            for (int mt = 0; mt < 2; mt++) {
                ldm_x4(ah[mt], base + 0 * PLANE_B + a_addr[mt] + kb);
                ldm_x4(av[mt], base + 1 * PLANE_B + a_addr[mt] + kb);
            }
            #pragma unroll
            for (int p = 0; p < 4; p++) {
                ldm_x4(bh[p], base + 2 * PLANE_B + b_addr[p] + kb);
                ldm_x4(bl[p], base + 3 * PLANE_B + b_addr[p] + kb);
            }
            // batch 1: hi*hi (16 MMAs, distinct accumulators)
            #pragma unroll
            for (int mt = 0; mt < 2; mt++)
                #pragma unroll
                for (int p = 0; p < 4; p++) {
                    uint32_t b0[2] = { bh[p][0], bh[p][2] };
                    uint32_t b1[2] = { bh[p][1], bh[p][3] };
                    mma16816(acc[mt][2*p+0], ah[mt], b0);
                    mma16816(acc[mt][2*p+1], ah[mt], b1);
                }
            // batch 2: hi*lo
            #pragma unroll
            for (int mt = 0; mt < 2; mt++)
                #pragma unroll
                for (int p = 0; p < 4; p++) {
                    uint32_t b0[2] = { bl[p][0], bl[p][2] };
                    uint32_t b1[2] = { bl[p][1], bl[p][3] };
                    mma16816(acc[mt][2*p+0], ah[mt], b0);
                    mma16816(acc[mt][2*p+1], ah[mt], b1);
                }
            // batch 3: lo*hi
            #pragma unroll
            for (int mt = 0; mt < 2; mt++)
                #pragma unroll
                for (int p = 0; p < 4; p++) {
                    uint32_t b0[2] = { bh[p][0], bh[p][2] };
                    uint32_t b1[2] = { bh[p][1], bh[p][3] };
                    mma16816(acc[mt][2*p+0], av[mt], b0);
                    mma16816(acc[mt][2*p+1], av[mt], b1);
                }
        }
        __syncthreads();   // all reads of buffer i&1 done before next overwrite
    }

    // epilogue
    const int g = lane >> 2, t = lane & 3;
    #pragma unroll
    for (int mt = 0; mt < 2; mt++) {
        int row = m0 + wm * 32 + mt * 16 + g;
        #pragma unroll
        for (int nt = 0; nt < 8; nt++) {
            int col = n0 + wn * 64 + nt * 8 + t * 2;
            float bx = bias[col], by = bias[col + 1];
            float* c = acc[mt][nt];
            float v0 = c[0] + bx, v1 = c[1] + by;
            float v2 = c[2] + bx, v3 = c[3] + by;
            if (SPLIT_OUT) {
                float s = (col < qcols) ? qscale : 1.0f;
                uint32_t h0, l0, h1, l1;
                split2(v0 * s, v1 * s, h0, l0);
                split2(v2 * s, v3 * s, h1, l1);
                *(uint32_t*)&Ch[(size_t)row * N + col] = h0;
                *(uint32_t*)&Cl[(size_t)row * N + col] = l0;
                *(uint32_t*)&Ch[(size_t)(row + 8) * N + col] = h1;
                *(uint32_t*)&Cl[(size_t)(row + 8) * N + col] = l1;
            } else {
                *(float2*)(Cf + (size_t)row * N + col) = make_float2(v0, v1);
                *(float2*)(Cf + (size_t)(row + 8) * N + col) = make_float2(v2, v3);
            }
        }
    }
}

// ================= HMMA flash attention (pre-split bf16 I/O) =================
#define KSTR 144
#define AQH 0
#define AQL (1 * 128 * KSTR)
#define AKH (2 * 128 * KSTR)
#define AKL (3 * 128 * KSTR)
#define AVH (4 * 128 * KSTR)
#define AVL (5 * 128 * KSTR)
#define ATT_SMEM (6 * 128 * KSTR)   // 110592

__global__ void __launch_bounds__(256)
attn_pre(const __nv_bfloat16* __restrict__ qkvh,
         const __nv_bfloat16* __restrict__ qkvl,
         __nv_bfloat16* __restrict__ atth,
         __nv_bfloat16* __restrict__ attl)
{
    extern __shared__ __align__(128) char smem[];
    const uint32_t sb = smem_u32(smem);
    const int tid = threadIdx.x;
    const int lane = tid & 31, wid = tid >> 5;
    const int b = blockIdx.y >> 4, h = blockIdx.y & 15;
    const int q0 = blockIdx.x * 128;

    const size_t rs = 3 * EMB;
    const __nv_bfloat16* Qh = qkvh + (size_t)(b * SEQ) * rs + h * HD;
    const __nv_bfloat16* Ql = qkvl + (size_t)(b * SEQ) * rs + h * HD;
    const __nv_bfloat16* Kh = Qh + EMB;
    const __nv_bfloat16* Kl = Ql + EMB;
    const __nv_bfloat16* Vh = Qh + 2 * EMB;
    const __nv_bfloat16* Vl = Ql + 2 * EMB;

    #pragma unroll
    for (int i = 0; i < 4; i++) {
        int idx = tid + i * 256;
        int r = idx >> 3, c16 = idx & 7;
        size_t go = (size_t)(q0 + r) * rs + c16 * 8;
        uint32_t so = r * KSTR + c16 * 16;
        *(uint4*)(smem + AQH + so) = *(const uint4*)(Qh + go);
        *(uint4*)(smem + AQL + so) = *(const uint4*)(Ql + go);
    }

    const int frow = lane & 15;
    const int fcol = ((lane >> 4) & 1) * 16;
    const uint32_t qa = sb + AQH + (uint32_t)((wid * 16 + frow) * KSTR + fcol);
    const uint32_t ka = sb + AKH + (uint32_t)(frow * KSTR + fcol);
    const uint32_t va = sb + AVH + (uint32_t)(frow * KSTR + fcol);
    const uint32_t QLO = AQL - AQH;
    const uint32_t KLO = AKL - AKH;
    const uint32_t VLO = AVL - AVH;

    float oacc[8][4] = {};
    float m0 = -1e30f, m1 = -1e30f;
    float l0 = 0.0f, l1 = 0.0f;

    for (int kt = 0; kt < SEQ / 128; kt++) {
        const int k0 = kt * 128;
        __syncthreads();

        #pragma unroll
        for (int i = 0; i < 4; i++) {
            int idx = tid + i * 256;
            int r = idx >> 3, c16 = idx & 7;
            size_t go = (size_t)(k0 + r) * rs + c16 * 8;
            uint32_t so = r * KSTR + c16 * 16;
            *(uint4*)(smem + AKH + so) = *(const uint4*)(Kh + go);
            *(uint4*)(smem + AKL + so) = *(const uint4*)(Kl + go);
            *(uint4*)(smem + AVH + so) = *(const uint4*)(Vh + go);
            *(uint4*)(smem + AVL + so) = *(const uint4*)(Vl + go);
        }
        __syncthreads();

        // ---- S = Q @ K^T, p-pair batches (acc reuse distance 4) ----
        float sacc[16][4] = {};
        #pragma unroll
        for (int kk = 0; kk < 4; kk++) {
            uint32_t aqh[4], aql[4];
            ldm_x4(aqh, qa + kk * 32);
            ldm_x4(aql, qa + QLO + kk * 32);
            #pragma unroll
            for (int pp = 0; pp < 4; pp++) {
                uint32_t khA[4], klA[4], khB[4], klB[4];
                ldm_x4(khA, ka + (2*pp+0) * (16 * KSTR) + kk * 32);
                ldm_x4(klA, ka + KLO + (2*pp+0) * (16 * KSTR) + kk * 32);
                ldm_x4(khB, ka + (2*pp+1) * (16 * KSTR) + kk * 32);
                ldm_x4(klB, ka + KLO + (2*pp+1) * (16 * KSTR) + kk * 32);
                uint32_t a0h[2] = { khA[0], khA[2] }, a1h[2] = { khA[1], khA[3] };
                uint32_t b0h[2] = { khB[0], khB[2] }, b1h[2] = { khB[1], khB[3] };
                uint32_t a0l[2] = { klA[0], klA[2] }, a1l[2] = { klA[1], klA[3] };
                uint32_t b0l[2] = { klB[0], klB[2] }, b1l[2] = { klB[1], klB[3] };
                // hh
                mma16816(sacc[4*pp+0], aqh, a0h);
                mma16816(sacc[4*pp+1], aqh, a1h);
                mma16816(sacc[4*pp+2], aqh, b0h);
                mma16816(sacc[4*pp+3], aqh, b1h);
                // hl
                mma16816(sacc[4*pp+0], aqh, a0l);
                mma16816(sacc[4*pp+1], aqh, a1l);
                mma16816(sacc[4*pp+2], aqh, b0l);
                mma16816(sacc[4*pp+3], aqh, b1l);
                // lh
                mma16816(sacc[4*pp+0], aql, a0h);
                mma16816(sacc[4*pp+1], aql, a1h);
                mma16816(sacc[4*pp+2], aql, b0h);
                mma16816(sacc[4*pp+3], aql, b1h);
            }
        }

        // ---- online softmax (base-2, warp-local) ----
        float mx0 = -1e30f, mx1 = -1e30f;
        #pragma unroll
        for (int nt = 0; nt < 16; nt++) {
            mx0 = fmaxf(mx0, fmaxf(sacc[nt][0], sacc[nt][1]));
            mx1 = fmaxf(mx1, fmaxf(sacc[nt][2], sacc[nt][3]));
        }
        mx0 = fmaxf(mx0, __shfl_xor_sync(0xffffffffu, mx0, 1));
        mx0 = fmaxf(mx0, __shfl_xor_sync(0xffffffffu, mx0, 2));
        mx1 = fmaxf(mx1, __shfl_xor_sync(0xffffffffu, mx1, 1));
        mx1 = fmaxf(mx1, __shfl_xor_sync(0xffffffffu, mx1, 2));
        float mn0 = fmaxf(m0, mx0), mn1 = fmaxf(m1, mx1);
        float a0 = exp2f(m0 - mn0), a1 = exp2f(m1 - mn1);
        m0 = mn0; m1 = mn1;

        float ls0 = 0.0f, ls1 = 0.0f;
        #pragma unroll
        for (int nt = 0; nt < 16; nt++) {
            sacc[nt][0] = exp2f(sacc[nt][0] - mn0);
            sacc[nt][1] = exp2f(sacc[nt][1] - mn0);
            sacc[nt][2] = exp2f(sacc[nt][2] - mn1);
            sacc[nt][3] = exp2f(sacc[nt][3] - mn1);
            ls0 += sacc[nt][0] + sacc[nt][1];
            ls1 += sacc[nt][2] + sacc[nt][3];
        }
        l0 = l0 * a0 + ls0;
        l1 = l1 * a1 + ls1;
        #pragma unroll
        for (int nt = 0; nt < 8; nt++) {
            oacc[nt][0] *= a0; oacc[nt][1] *= a0;
            oacc[nt][2] *= a1; oacc[nt][3] *= a1;
        }

        // ---- O += P @ V; nd-pair batches (acc reuse distance 4) ----
        #pragma unroll
        for (int kk = 0; kk < 8; kk++) {
            uint32_t ph[4], pl[4];
            split2(sacc[2*kk  ][0], sacc[2*kk  ][1], ph[0], pl[0]);
            split2(sacc[2*kk  ][2], sacc[2*kk  ][3], ph[1], pl[1]);
            split2(sacc[2*kk+1][0], sacc[2*kk+1][1], ph[2], pl[2]);
            split2(sacc[2*kk+1][2], sacc[2*kk+1][3], ph[3], pl[3]);
            #pragma unroll
            for (int np = 0; np < 2; np++) {
                uint32_t vhA[4], vlA[4], vhB[4], vlB[4];
                ldm_x4_t(vhA, va + kk * (16 * KSTR) + (2*np+0) * 32);
                ldm_x4_t(vlA, va + VLO + kk * (16 * KSTR) + (2*np+0) * 32);
                ldm_x4_t(vhB, va + kk * (16 * KSTR) + (2*np+1) * 32);
                ldm_x4_t(vlB, va + VLO + kk * (16 * KSTR) + (2*np+1) * 32);
                uint32_t a0h[2] = { vhA[0], vhA[1] }, a1h[2] = { vhA[2], vhA[3] };
                uint32_t b0h[2] = { vhB[0], vhB[1] }, b1h[2] = { vhB[2], vhB[3] };
                uint32_t a0l[2] = { vlA[0], vlA[1] }, a1l[2] = { vlA[2], vlA[3] };
                uint32_t b0l[2] = { vlB[0], vlB[1] }, b1l[2] = { vlB[2], vlB[3] };
                // hh
                mma16816(oacc[4*np+0], ph, a0h);
                mma16816(oacc[4*np+1], ph, a1h);
                mma16816(oacc[4*np+2], ph, b0h);
                mma16816(oacc[4*np+3], ph, b1h);
                // hl
                mma16816(oacc[4*np+0], ph, a0l);
                mma16816(oacc[4*np+1], ph, a1l);
                mma16816(oacc[4*np+2], ph, b0l);
                mma16816(oacc[4*np+3], ph, b1l);
                // lh
                mma16816(oacc[4*np+0], pl, a0h);
                mma16816(oacc[4*np+1], pl, a1h);
                mma16816(oacc[4*np+2], pl, b0h);
                mma16816(oacc[4*np+3], pl, b1h);
            }
        }
    }

    // ---- finalize ----
    l0 += __shfl_xor_sync(0xffffffffu, l0, 1);
    l0 += __shfl_xor_sync(0xffffffffu, l0, 2);
    l1 += __shfl_xor_sync(0xffffffffu, l1, 1);
    l1 += __shfl_xor_sync(0xffffffffu, l1, 2);
    float inv0 = 1.0f / l0, inv1 = 1.0f / l1;

    const int g = lane >> 2, t = lane & 3;
    const int row = q0 + wid * 16 + g;
    size_t o0 = (size_t)(b * SEQ + row) * EMB + h * HD;
    size_t o1 = (size_t)(b * SEQ + row + 8) * EMB + h * HD;
    #pragma unroll
    for (int nt = 0; nt < 8; nt++) {
        int col = nt * 8 + t * 2;
        uint32_t h0, lo0, h1, lo1;
        split2(oacc[nt][0] * inv0, oacc[nt][1] * inv0, h0, lo0);
        split2(oacc[nt][2] * inv1, oacc[nt][3] * inv1, h1, lo1);
        *(uint32_t*)&atth[o0 + col] = h0;
        *(uint32_t*)&attl[o0 + col] = lo0;
        *(uint32_t*)&atth[o1 + col] = h1;
        *(uint32_t*)&attl[o1 + col] = lo1;
    }
}

// ---------------------------------------------------------------------------
extern "C" void kernel_launch(void* const* d_in, const int* in_sizes, int n_in,
                              void* d_out, int out_size)
{
    const float* x      = (const float*)d_in[0];
    const float* w_qkv  = (const float*)d_in[1];
    const float* b_qkv  = (const float*)d_in[2];
    const float* w_proj = (const float*)d_in[3];
    const float* b_proj = (const float*)d_in[4];
    float* out = (float*)d_out;

    __nv_bfloat16 *xh, *xl, *wqh, *wql, *wph, *wpl, *qh, *ql, *ath, *atl;
    cudaGetSymbolAddress((void**)&xh, g_xh);
    cudaGetSymbolAddress((void**)&xl, g_xl);
    cudaGetSymbolAddress((void**)&wqh, g_wqh);
    cudaGetSymbolAddress((void**)&wql, g_wql);
    cudaGetSymbolAddress((void**)&wph, g_wph);
    cudaGetSymbolAddress((void**)&wpl, g_wpl);
    cudaGetSymbolAddress((void**)&qh, g_qkvh);
    cudaGetSymbolAddress((void**)&ql, g_qkvl);
    cudaGetSymbolAddress((void**)&ath, g_atth);
    cudaGetSymbolAddress((void**)&atl, g_attl);

    cudaFuncSetAttribute(gemm_pre<true>,  cudaFuncAttributeMaxDynamicSharedMemorySize, GEMM_SMEM);
    cudaFuncSetAttribute(gemm_pre<false>, cudaFuncAttributeMaxDynamicSharedMemorySize, GEMM_SMEM);
    cudaFuncSetAttribute(attn_pre, cudaFuncAttributeMaxDynamicSharedMemorySize, ATT_SMEM);

    // 0) pre-split operands
    {
        int n4 = TOK * EMB / 4;
        split_f32<<<(n4 + 255) / 256, 256>>>(x, xh, xl, n4);
        n4 = 3 * EMB * EMB / 4;
        split_f32<<<(n4 + 255) / 256, 256>>>(w_qkv, wqh, wql, n4);
        n4 = EMB * EMB / 4;
        split_f32<<<(n4 + 255) / 256, 256>>>(w_proj, wph, wpl, n4);
    }

    const float QSCALE = 0.125f * 1.4426950408889634f;   // 1/sqrt(64) * log2(e)

    // 1) QKV projection -> split bf16 qkv (Q columns pre-scaled)
    dim3 g1(3 * EMB / 128, TOK / 128);
    gemm_pre<true><<<g1, 256, GEMM_SMEM>>>(xh, xl, wqh, wql, b_qkv,
                                           nullptr, qh, ql,
                                           TOK, 3 * EMB, EMB, EMB, QSCALE);

    // 2) Attention -> split bf16 att
    dim3 g2(SEQ / 128, BATCH * NH);
    attn_pre<<<g2, 256, ATT_SMEM>>>(qh, ql, ath, atl);

    // 3) Output projection -> fp32 out
    dim3 g3(EMB / 128, TOK / 128);
    gemm_pre<false><<<g3, 256, GEMM_SMEM>>>(ath, atl, wph, wpl, b_proj,
                                            out, nullptr, nullptr,
                                            TOK, EMB, EMB, 0, 1.0f);
}

// round 7
// speedup vs baseline: 2.9203x; 1.0935x over previous
#include <cuda_runtime.h>
#include <cuda_bf16.h>
#include <cstdint>

#define BATCH 4
#define SEQ   2048
#define EMB   1024
#define NH    16
#define HD    64
#define TOK   (BATCH*SEQ)      // 8192

// ---------------- scratch (device globals; allocation-free rule) ----------
__device__ __nv_bfloat16 g_xh[(size_t)TOK * EMB];
__device__ __nv_bfloat16 g_xl[(size_t)TOK * EMB];
__device__ __nv_bfloat16 g_wqh[(size_t)3 * EMB * EMB];
__device__ __nv_bfloat16 g_wql[(size_t)3 * EMB * EMB];
__device__ __nv_bfloat16 g_wph[(size_t)EMB * EMB];
__device__ __nv_bfloat16 g_wpl[(size_t)EMB * EMB];
__device__ __nv_bfloat16 g_qkvh[(size_t)TOK * 3 * EMB];
__device__ __nv_bfloat16 g_qkvl[(size_t)TOK * 3 * EMB];
__device__ __nv_bfloat16 g_atth[(size_t)TOK * EMB];
__device__ __nv_bfloat16 g_attl[(size_t)TOK * EMB];

// ---------------- primitives ----------------
__device__ __forceinline__ uint32_t smem_u32(const void* p) {
    uint32_t a;
    asm("{ .reg .u64 t; cvta.to.shared.u64 t, %1; cvt.u32.u64 %0, t; }" : "=r"(a) : "l"(p));
    return a;
}
__device__ __forceinline__ void ldm_x4(uint32_t* r, uint32_t addr) {
    asm volatile("ldmatrix.sync.aligned.m8n8.x4.shared.b16 {%0,%1,%2,%3}, [%4];"
        : "=r"(r[0]), "=r"(r[1]), "=r"(r[2]), "=r"(r[3]) : "r"(addr));
}
__device__ __forceinline__ void ldm_x4_t(uint32_t* r, uint32_t addr) {
    asm volatile("ldmatrix.sync.aligned.m8n8.x4.trans.shared.b16 {%0,%1,%2,%3}, [%4];"
        : "=r"(r[0]), "=r"(r[1]), "=r"(r[2]), "=r"(r[3]) : "r"(addr));
}
__device__ __forceinline__ void mma16816(float* c, const uint32_t* a, const uint32_t* b) {
    asm volatile(
        "mma.sync.aligned.m16n8k16.row.col.f32.bf16.bf16.f32 "
        "{%0,%1,%2,%3}, {%4,%5,%6,%7}, {%8,%9}, {%0,%1,%2,%3};"
        : "+f"(c[0]), "+f"(c[1]), "+f"(c[2]), "+f"(c[3])
        : "r"(a[0]), "r"(a[1]), "r"(a[2]), "r"(a[3]), "r"(b[0]), "r"(b[1]));
}
#define CP16(dst, src) \
    asm volatile("cp.async.cg.shared.global [%0], [%1], 16;" \
        :: "r"(dst), "l"(src) : "memory")

__device__ __forceinline__ void cvt_split(float4 v, uint2& hi, uint2& lo) {
    __nv_bfloat162 h0 = __floats2bfloat162_rn(v.x, v.y);
    __nv_bfloat162 h1 = __floats2bfloat162_rn(v.z, v.w);
    float rx = __bfloat162float(h0.x), ry = __bfloat162float(h0.y);
    float rz = __bfloat162float(h1.x), rw = __bfloat162float(h1.y);
    __nv_bfloat162 l0 = __floats2bfloat162_rn(v.x - rx, v.y - ry);
    __nv_bfloat162 l1 = __floats2bfloat162_rn(v.z - rz, v.w - rw);
    hi.x = *(uint32_t*)&h0; hi.y = *(uint32_t*)&h1;
    lo.x = *(uint32_t*)&l0; lo.y = *(uint32_t*)&l1;
}
__device__ __forceinline__ void split2(float x, float y, uint32_t& h, uint32_t& l) {
    __nv_bfloat162 hh = __floats2bfloat162_rn(x, y);
    h = *(uint32_t*)&hh;
    __nv_bfloat162 ll = __floats2bfloat162_rn(x - __bfloat162float(hh.x),
                                              y - __bfloat162float(hh.y));
    l = *(uint32_t*)&ll;
}

// ---------------- fp32 -> split bf16 planes ----------------
__global__ void __launch_bounds__(256)
split_f32(const float* __restrict__ in, __nv_bfloat16* __restrict__ h,
          __nv_bfloat16* __restrict__ l, int n4)
{
    int i = blockIdx.x * blockDim.x + threadIdx.x;
    if (i < n4) {
        float4 v = ((const float4*)in)[i];
        uint2 hi, lo;
        cvt_split(v, hi, lo);
        ((uint2*)h)[i] = hi;
        ((uint2*)l)[i] = lo;
    }
}

// ================= pre-split GEMM, cp.async, 2 CTAs/SM, low-reg =================
#define ROWB    80
#define PLANE_B (128 * ROWB)      // 10240
#define BUF_B   (4 * PLANE_B)     // 40960
#define GEMM_SMEM (2 * BUF_B)     // 81920 -> 2 CTAs/SM

template<bool SPLIT_OUT>
__global__ void __launch_bounds__(256, 2)
gemm_pre(const __nv_bfloat16* __restrict__ Ah, const __nv_bfloat16* __restrict__ Al,
         const __nv_bfloat16* __restrict__ Wh, const __nv_bfloat16* __restrict__ Wl,
         const float* __restrict__ bias,
         float* __restrict__ Cf,
         __nv_bfloat16* __restrict__ Ch, __nv_bfloat16* __restrict__ Cl,
         int M, int N, int K, int qcols, float qscale)
{
    extern __shared__ __align__(128) char smem[];
    const uint32_t sb = smem_u32(smem);
    const int tid = threadIdx.x;
    const int lane = tid & 31, wid = tid >> 5;
    const int wm = wid >> 1, wn = wid & 1;
    const int m0 = blockIdx.y * 128;
    const int n0 = blockIdx.x * 128;

    float acc[2][8][4] = {};

    const int frow = lane & 15;
    const int fcol = ((lane >> 4) & 1) * 16;
    uint32_t a_addr[2], b_addr[4];
    #pragma unroll
    for (int mt = 0; mt < 2; mt++)
        a_addr[mt] = (uint32_t)((wm * 32 + mt * 16 + frow) * ROWB + fcol);
    #pragma unroll
    for (int p = 0; p < 4; p++)
        b_addr[p] = (uint32_t)((wn * 64 + p * 16 + frow) * ROWB + fcol);

    auto issue = [&](int stage, int k0) {
        const uint32_t sbuf = sb + stage * BUF_B;
        #pragma unroll
        for (int j = 0; j < 2; j++) {
            int cid = tid + j * 256;
            int r = cid >> 2, c16 = cid & 3;
            uint32_t so = (uint32_t)(r * ROWB + c16 * 16);
            size_t ga = (size_t)(m0 + r) * K + k0 + c16 * 8;
            size_t gb = (size_t)(n0 + r) * K + k0 + c16 * 8;
            CP16(sbuf + 0 * PLANE_B + so, Ah + ga);
            CP16(sbuf + 1 * PLANE_B + so, Al + ga);
            CP16(sbuf + 2 * PLANE_B + so, Wh + gb);
            CP16(sbuf + 3 * PLANE_B + so, Wl + gb);
        }
        asm volatile("cp.async.commit_group;" ::: "memory");
    };

    const int nch = K / 32;
    issue(0, 0);

    for (int i = 0; i < nch; i++) {
        if (i + 1 < nch) issue((i + 1) & 1, (i + 1) * 32);
        else asm volatile("cp.async.commit_group;" ::: "memory");
        asm volatile("cp.async.wait_group 1;" ::: "memory");
        __syncthreads();

        const uint32_t base = sb + (i & 1) * BUF_B;
        #pragma unroll
        for (int kh = 0; kh < 2; kh++) {
            const uint32_t kb = kh * 32;
            uint32_t ah[2][4], av[2][4], bb[4][4];
            #pragma unroll
            for (int mt = 0; mt < 2; mt++) {
                ldm_x4(ah[mt], base + 0 * PLANE_B + a_addr[mt] + kb);
                ldm_x4(av[mt], base + 1 * PLANE_B + a_addr[mt] + kb);
            }
            // ---- bb = B_hi ----
            #pragma unroll
            for (int p = 0; p < 4; p++)
                ldm_x4(bb[p], base + 2 * PLANE_B + b_addr[p] + kb);
            // hh
            #pragma unroll
            for (int mt = 0; mt < 2; mt++)
                #pragma unroll
                for (int p = 0; p < 4; p++) {
                    uint32_t b0[2] = { bb[p][0], bb[p][2] };
                    uint32_t b1[2] = { bb[p][1], bb[p][3] };
                    mma16816(acc[mt][2*p+0], ah[mt], b0);
                    mma16816(acc[mt][2*p+1], ah[mt], b1);
                }
            // lh (A_lo * B_hi)
            #pragma unroll
            for (int mt = 0; mt < 2; mt++)
                #pragma unroll
                for (int p = 0; p < 4; p++) {
                    uint32_t b0[2] = { bb[p][0], bb[p][2] };
                    uint32_t b1[2] = { bb[p][1], bb[p][3] };
                    mma16816(acc[mt][2*p+0], av[mt], b0);
                    mma16816(acc[mt][2*p+1], av[mt], b1);
                }
            // ---- bb = B_lo (reuse regs) ----
            #pragma unroll
            for (int p = 0; p < 4; p++)
                ldm_x4(bb[p], base + 3 * PLANE_B + b_addr[p] + kb);
            // hl (A_hi * B_lo)
            #pragma unroll
            for (int mt = 0; mt < 2; mt++)
                #pragma unroll
                for (int p = 0; p < 4; p++) {
                    uint32_t b0[2] = { bb[p][0], bb[p][2] };
                    uint32_t b1[2] = { bb[p][1], bb[p][3] };
                    mma16816(acc[mt][2*p+0], ah[mt], b0);
                    mma16816(acc[mt][2*p+1], ah[mt], b1);
                }
        }
        __syncthreads();
    }

    // epilogue
    const int g = lane >> 2, t = lane & 3;
    #pragma unroll
    for (int mt = 0; mt < 2; mt++) {
        int row = m0 + wm * 32 + mt * 16 + g;
        #pragma unroll
        for (int nt = 0; nt < 8; nt++) {
            int col = n0 + wn * 64 + nt * 8 + t * 2;
            float bx = bias[col], by = bias[col + 1];
            float* c = acc[mt][nt];
            float v0 = c[0] + bx, v1 = c[1] + by;
            float v2 = c[2] + bx, v3 = c[3] + by;
            if (SPLIT_OUT) {
                float s = (col < qcols) ? qscale : 1.0f;
                uint32_t h0, l0, h1, l1;
                split2(v0 * s, v1 * s, h0, l0);
                split2(v2 * s, v3 * s, h1, l1);
                *(uint32_t*)&Ch[(size_t)row * N + col] = h0;
                *(uint32_t*)&Cl[(size_t)row * N + col] = l0;
                *(uint32_t*)&Ch[(size_t)(row + 8) * N + col] = h1;
                *(uint32_t*)&Cl[(size_t)(row + 8) * N + col] = l1;
            } else {
                *(float2*)(Cf + (size_t)row * N + col) = make_float2(v0, v1);
                *(float2*)(Cf + (size_t)(row + 8) * N + col) = make_float2(v2, v3);
            }
        }
    }
}

// ================= HMMA flash attention: key tile 64, 2 CTAs/SM =================
// CTA = 128 queries of one (b,h); 32 key tiles of 64. 8 warps, warp-local softmax.
#define KSTR 144
#define AQH 0
#define AQL (1 * 128 * KSTR)
#define AKH (2 * 128 * KSTR)                 // K planes: 64 rows each
#define AKL (AKH + 64 * KSTR)
#define AVH (AKL + 64 * KSTR)
#define AVL (AVH + 64 * KSTR)
#define ATT_SMEM (AVL + 64 * KSTR)           // 73728 -> 2 CTAs/SM

__global__ void __launch_bounds__(256, 2)
attn_pre(const __nv_bfloat16* __restrict__ qkvh,
         const __nv_bfloat16* __restrict__ qkvl,
         __nv_bfloat16* __restrict__ atth,
         __nv_bfloat16* __restrict__ attl)
{
    extern __shared__ __align__(128) char smem[];
    const uint32_t sb = smem_u32(smem);
    const int tid = threadIdx.x;
    const int lane = tid & 31, wid = tid >> 5;
    const int b = blockIdx.y >> 4, h = blockIdx.y & 15;
    const int q0 = blockIdx.x * 128;

    const size_t rs = 3 * EMB;
    const __nv_bfloat16* Qh = qkvh + (size_t)(b * SEQ) * rs + h * HD;
    const __nv_bfloat16* Ql = qkvl + (size_t)(b * SEQ) * rs + h * HD;
    const __nv_bfloat16* Kh = Qh + EMB;
    const __nv_bfloat16* Kl = Ql + EMB;
    const __nv_bfloat16* Vh = Qh + 2 * EMB;
    const __nv_bfloat16* Vl = Ql + 2 * EMB;

    // ---- load Q tile (128 rows) ----
    #pragma unroll
    for (int i = 0; i < 4; i++) {
        int idx = tid + i * 256;
        int r = idx >> 3, c16 = idx & 7;
        size_t go = (size_t)(q0 + r) * rs + c16 * 8;
        uint32_t so = r * KSTR + c16 * 16;
        *(uint4*)(smem + AQH + so) = *(const uint4*)(Qh + go);
        *(uint4*)(smem + AQL + so) = *(const uint4*)(Ql + go);
    }

    const int frow = lane & 15;
    const int fcol = ((lane >> 4) & 1) * 16;
    const uint32_t qa = sb + AQH + (uint32_t)((wid * 16 + frow) * KSTR + fcol);
    const uint32_t ka = sb + AKH + (uint32_t)(frow * KSTR + fcol);
    const uint32_t va = sb + AVH + (uint32_t)(frow * KSTR + fcol);
    const uint32_t QLO = AQL - AQH;
    const uint32_t KLO = AKL - AKH;
    const uint32_t VLO = AVL - AVH;

    float oacc[8][4] = {};
    float m0 = -1e30f, m1 = -1e30f;
    float l0 = 0.0f, l1 = 0.0f;

    for (int kt = 0; kt < SEQ / 64; kt++) {
        const int k0 = kt * 64;
        __syncthreads();

        // ---- load K and V tiles (64 rows, 16B copies) ----
        #pragma unroll
        for (int i = 0; i < 2; i++) {
            int idx = tid + i * 256;           // 0..511
            int r = idx >> 3, c16 = idx & 7;
            size_t go = (size_t)(k0 + r) * rs + c16 * 8;
            uint32_t so = r * KSTR + c16 * 16;
            *(uint4*)(smem + AKH + so) = *(const uint4*)(Kh + go);
            *(uint4*)(smem + AKL + so) = *(const uint4*)(Kl + go);
            *(uint4*)(smem + AVH + so) = *(const uint4*)(Vh + go);
            *(uint4*)(smem + AVL + so) = *(const uint4*)(Vl + go);
        }
        __syncthreads();

        // ---- S = Q @ K^T (16 x 64 per warp) ----
        float sacc[8][4] = {};
        #pragma unroll
        for (int kk = 0; kk < 4; kk++) {
            uint32_t aqh[4], aql[4], kf[4][4];
            ldm_x4(aqh, qa + kk * 32);
            ldm_x4(aql, qa + QLO + kk * 32);
            // kf = K_hi
            #pragma unroll
            for (int p = 0; p < 4; p++)
                ldm_x4(kf[p], ka + p * (16 * KSTR) + kk * 32);
            // hh
            #pragma unroll
            for (int p = 0; p < 4; p++) {
                uint32_t b0[2] = { kf[p][0], kf[p][2] };
                uint32_t b1[2] = { kf[p][1], kf[p][3] };
                mma16816(sacc[2*p+0], aqh, b0);
                mma16816(sacc[2*p+1], aqh, b1);
            }
            // lh (Q_lo * K_hi)
            #pragma unroll
            for (int p = 0; p < 4; p++) {
                uint32_t b0[2] = { kf[p][0], kf[p][2] };
                uint32_t b1[2] = { kf[p][1], kf[p][3] };
                mma16816(sacc[2*p+0], aql, b0);
                mma16816(sacc[2*p+1], aql, b1);
            }
            // kf = K_lo
            #pragma unroll
            for (int p = 0; p < 4; p++)
                ldm_x4(kf[p], ka + KLO + p * (16 * KSTR) + kk * 32);
            // hl
            #pragma unroll
            for (int p = 0; p < 4; p++) {
                uint32_t b0[2] = { kf[p][0], kf[p][2] };
                uint32_t b1[2] = { kf[p][1], kf[p][3] };
                mma16816(sacc[2*p+0], aqh, b0);
                mma16816(sacc[2*p+1], aqh, b1);
            }
        }

        // ---- online softmax (base-2, warp-local) ----
        float mx0 = -1e30f, mx1 = -1e30f;
        #pragma unroll
        for (int nt = 0; nt < 8; nt++) {
            mx0 = fmaxf(mx0, fmaxf(sacc[nt][0], sacc[nt][1]));
            mx1 = fmaxf(mx1, fmaxf(sacc[nt][2], sacc[nt][3]));
        }
        mx0 = fmaxf(mx0, __shfl_xor_sync(0xffffffffu, mx0, 1));
        mx0 = fmaxf(mx0, __shfl_xor_sync(0xffffffffu, mx0, 2));
        mx1 = fmaxf(mx1, __shfl_xor_sync(0xffffffffu, mx1, 1));
        mx1 = fmaxf(mx1, __shfl_xor_sync(0xffffffffu, mx1, 2));
        float mn0 = fmaxf(m0, mx0), mn1 = fmaxf(m1, mx1);
        float a0 = exp2f(m0 - mn0), a1 = exp2f(m1 - mn1);
        m0 = mn0; m1 = mn1;

        float ls0 = 0.0f, ls1 = 0.0f;
        #pragma unroll
        for (int nt = 0; nt < 8; nt++) {
            sacc[nt][0] = exp2f(sacc[nt][0] - mn0);
            sacc[nt][1] = exp2f(sacc[nt][1] - mn0);
            sacc[nt][2] = exp2f(sacc[nt][2] - mn1);
            sacc[nt][3] = exp2f(sacc[nt][3] - mn1);
            ls0 += sacc[nt][0] + sacc[nt][1];
            ls1 += sacc[nt][2] + sacc[nt][3];
        }
        l0 = l0 * a0 + ls0;
        l1 = l1 * a1 + ls1;
        #pragma unroll
        for (int nt = 0; nt < 8; nt++) {
            oacc[nt][0] *= a0; oacc[nt][1] *= a0;
            oacc[nt][2] *= a1; oacc[nt][3] *= a1;
        }

        // ---- O += P @ V (V via ldmatrix.trans; reuse V regs) ----
        #pragma unroll
        for (int kk = 0; kk < 4; kk++) {
            uint32_t ph[4], pl[4], vf[4][4];
            split2(sacc[2*kk  ][0], sacc[2*kk  ][1], ph[0], pl[0]);
            split2(sacc[2*kk  ][2], sacc[2*kk  ][3], ph[1], pl[1]);
            split2(sacc[2*kk+1][0], sacc[2*kk+1][1], ph[2], pl[2]);
            split2(sacc[2*kk+1][2], sacc[2*kk+1][3], ph[3], pl[3]);
            // vf = V_hi
            #pragma unroll
            for (int nd = 0; nd < 4; nd++)
                ldm_x4_t(vf[nd], va + kk * (16 * KSTR) + nd * 32);
            // hh
            #pragma unroll
            for (int nd = 0; nd < 4; nd++) {
                uint32_t b0[2] = { vf[nd][0], vf[nd][1] };
                uint32_t b1[2] = { vf[nd][2], vf[nd][3] };
                mma16816(oacc[2*nd+0], ph, b0);
                mma16816(oacc[2*nd+1], ph, b1);
            }
            // lh (P_lo * V_hi)
            #pragma unroll
            for (int nd = 0; nd < 4; nd++) {
                uint32_t b0[2] = { vf[nd][0], vf[nd][1] };
                uint32_t b1[2] = { vf[nd][2], vf[nd][3] };
                mma16816(oacc[2*nd+0], pl, b0);
                mma16816(oacc[2*nd+1], pl, b1);
            }
            // vf = V_lo
            #pragma unroll
            for (int nd = 0; nd < 4; nd++)
                ldm_x4_t(vf[nd], va + VLO + kk * (16 * KSTR) + nd * 32);
            // hl
            #pragma unroll
            for (int nd = 0; nd < 4; nd++) {
                uint32_t b0[2] = { vf[nd][0], vf[nd][1] };
                uint32_t b1[2] = { vf[nd][2], vf[nd][3] };
                mma16816(oacc[2*nd+0], ph, b0);
                mma16816(oacc[2*nd+1], ph, b1);
            }
        }
    }

    // ---- finalize ----
    l0 += __shfl_xor_sync(0xffffffffu, l0, 1);
    l0 += __shfl_xor_sync(0xffffffffu, l0, 2);
    l1 += __shfl_xor_sync(0xffffffffu, l1, 1);
    l1 += __shfl_xor_sync(0xffffffffu, l1, 2);
    float inv0 = 1.0f / l0, inv1 = 1.0f / l1;

    const int g = lane >> 2, t = lane & 3;
    const int row = q0 + wid * 16 + g;
    size_t o0 = (size_t)(b * SEQ + row) * EMB + h * HD;
    size_t o1 = (size_t)(b * SEQ + row + 8) * EMB + h * HD;
    #pragma unroll
    for (int nt = 0; nt < 8; nt++) {
        int col = nt * 8 + t * 2;
        uint32_t h0, lo0, h1, lo1;
        split2(oacc[nt][0] * inv0, oacc[nt][1] * inv0, h0, lo0);
        split2(oacc[nt][2] * inv1, oacc[nt][3] * inv1, h1, lo1);
        *(uint32_t*)&atth[o0 + col] = h0;
        *(uint32_t*)&attl[o0 + col] = lo0;
        *(uint32_t*)&atth[o1 + col] = h1;
        *(uint32_t*)&attl[o1 + col] = lo1;
    }
}

// ---------------------------------------------------------------------------
extern "C" void kernel_launch(void* const* d_in, const int* in_sizes, int n_in,
                              void* d_out, int out_size)
{
    const float* x      = (const float*)d_in[0];
    const float* w_qkv  = (const float*)d_in[1];
    const float* b_qkv  = (const float*)d_in[2];
    const float* w_proj = (const float*)d_in[3];
    const float* b_proj = (const float*)d_in[4];
    float* out = (float*)d_out;

    __nv_bfloat16 *xh, *xl, *wqh, *wql, *wph, *wpl, *qh, *ql, *ath, *atl;
    cudaGetSymbolAddress((void**)&xh, g_xh);
    cudaGetSymbolAddress((void**)&xl, g_xl);
    cudaGetSymbolAddress((void**)&wqh, g_wqh);
    cudaGetSymbolAddress((void**)&wql, g_wql);
    cudaGetSymbolAddress((void**)&wph, g_wph);
    cudaGetSymbolAddress((void**)&wpl, g_wpl);
    cudaGetSymbolAddress((void**)&qh, g_qkvh);
    cudaGetSymbolAddress((void**)&ql, g_qkvl);
    cudaGetSymbolAddress((void**)&ath, g_atth);
    cudaGetSymbolAddress((void**)&atl, g_attl);

    cudaFuncSetAttribute(gemm_pre<true>,  cudaFuncAttributeMaxDynamicSharedMemorySize, GEMM_SMEM);
    cudaFuncSetAttribute(gemm_pre<false>, cudaFuncAttributeMaxDynamicSharedMemorySize, GEMM_SMEM);
    cudaFuncSetAttribute(attn_pre, cudaFuncAttributeMaxDynamicSharedMemorySize, ATT_SMEM);

    // 0) pre-split operands
    {
        int n4 = TOK * EMB / 4;
        split_f32<<<(n4 + 255) / 256, 256>>>(x, xh, xl, n4);
        n4 = 3 * EMB * EMB / 4;
        split_f32<<<(n4 + 255) / 256, 256>>>(w_qkv, wqh, wql, n4);
        n4 = EMB * EMB / 4;
        split_f32<<<(n4 + 255) / 256, 256>>>(w_proj, wph, wpl, n4);
    }

    const float QSCALE = 0.125f * 1.4426950408889634f;   // 1/sqrt(64) * log2(e)

    // 1) QKV projection -> split bf16 qkv (Q columns pre-scaled)
    dim3 g1(3 * EMB / 128, TOK / 128);
    gemm_pre<true><<<g1, 256, GEMM_SMEM>>>(xh, xl, wqh, wql, b_qkv,
                                           nullptr, qh, ql,
                                           TOK, 3 * EMB, EMB, EMB, QSCALE);

    // 2) Attention -> split bf16 att
    dim3 g2(SEQ / 128, BATCH * NH);
    attn_pre<<<g2, 256, ATT_SMEM>>>(qh, ql, ath, atl);

    // 3) Output projection -> fp32 out
    dim3 g3(EMB / 128, TOK / 128);
    gemm_pre<false><<<g3, 256, GEMM_SMEM>>>(ath, atl, wph, wpl, b_proj,
                                            out, nullptr, nullptr,
                                            TOK, EMB, EMB, 0, 1.0f);
}

// round 8
// speedup vs baseline: 2.9438x; 1.0080x over previous
#include <cuda_runtime.h>
#include <cuda_bf16.h>
#include <cstdint>

#define BATCH 4
#define SEQ   2048
#define EMB   1024
#define NH    16
#define HD    64
#define TOK   (BATCH*SEQ)      // 8192

// ---------------- scratch (device globals; allocation-free rule) ----------
__device__ __nv_bfloat16 g_xh[(size_t)TOK * EMB];
__device__ __nv_bfloat16 g_xl[(size_t)TOK * EMB];
__device__ __nv_bfloat16 g_wqh[(size_t)3 * EMB * EMB];
__device__ __nv_bfloat16 g_wql[(size_t)3 * EMB * EMB];
__device__ __nv_bfloat16 g_wph[(size_t)EMB * EMB];
__device__ __nv_bfloat16 g_wpl[(size_t)EMB * EMB];
__device__ __nv_bfloat16 g_qkvh[(size_t)TOK * 3 * EMB];
__device__ __nv_bfloat16 g_qkvl[(size_t)TOK * 3 * EMB];
__device__ __nv_bfloat16 g_atth[(size_t)TOK * EMB];
__device__ __nv_bfloat16 g_attl[(size_t)TOK * EMB];

// ---------------- primitives ----------------
__device__ __forceinline__ uint32_t smem_u32(const void* p) {
    uint32_t a;
    asm("{ .reg .u64 t; cvta.to.shared.u64 t, %1; cvt.u32.u64 %0, t; }" : "=r"(a) : "l"(p));
    return a;
}
__device__ __forceinline__ void ldm_x4(uint32_t* r, uint32_t addr) {
    asm volatile("ldmatrix.sync.aligned.m8n8.x4.shared.b16 {%0,%1,%2,%3}, [%4];"
        : "=r"(r[0]), "=r"(r[1]), "=r"(r[2]), "=r"(r[3]) : "r"(addr));
}
__device__ __forceinline__ void ldm_x4_t(uint32_t* r, uint32_t addr) {
    asm volatile("ldmatrix.sync.aligned.m8n8.x4.trans.shared.b16 {%0,%1,%2,%3}, [%4];"
        : "=r"(r[0]), "=r"(r[1]), "=r"(r[2]), "=r"(r[3]) : "r"(addr));
}
__device__ __forceinline__ void mma16816(float* c, const uint32_t* a, const uint32_t* b) {
    asm volatile(
        "mma.sync.aligned.m16n8k16.row.col.f32.bf16.bf16.f32 "
        "{%0,%1,%2,%3}, {%4,%5,%6,%7}, {%8,%9}, {%0,%1,%2,%3};"
        : "+f"(c[0]), "+f"(c[1]), "+f"(c[2]), "+f"(c[3])
        : "r"(a[0]), "r"(a[1]), "r"(a[2]), "r"(a[3]), "r"(b[0]), "r"(b[1]));
}
#define CP16(dst, src) \
    asm volatile("cp.async.cg.shared.global [%0], [%1], 16;" \
        :: "r"(dst), "l"(src) : "memory")
#define CP_COMMIT() asm volatile("cp.async.commit_group;" ::: "memory")
#define CP_WAIT0()  asm volatile("cp.async.wait_group 0;" ::: "memory")

__device__ __forceinline__ void cvt_split(float4 v, uint2& hi, uint2& lo) {
    __nv_bfloat162 h0 = __floats2bfloat162_rn(v.x, v.y);
    __nv_bfloat162 h1 = __floats2bfloat162_rn(v.z, v.w);
    float rx = __bfloat162float(h0.x), ry = __bfloat162float(h0.y);
    float rz = __bfloat162float(h1.x), rw = __bfloat162float(h1.y);
    __nv_bfloat162 l0 = __floats2bfloat162_rn(v.x - rx, v.y - ry);
    __nv_bfloat162 l1 = __floats2bfloat162_rn(v.z - rz, v.w - rw);
    hi.x = *(uint32_t*)&h0; hi.y = *(uint32_t*)&h1;
    lo.x = *(uint32_t*)&l0; lo.y = *(uint32_t*)&l1;
}
__device__ __forceinline__ void split2(float x, float y, uint32_t& h, uint32_t& l) {
    __nv_bfloat162 hh = __floats2bfloat162_rn(x, y);
    h = *(uint32_t*)&hh;
    __nv_bfloat162 ll = __floats2bfloat162_rn(x - __bfloat162float(hh.x),
                                              y - __bfloat162float(hh.y));
    l = *(uint32_t*)&ll;
}

// ---------------- fp32 -> split bf16 planes ----------------
__global__ void __launch_bounds__(256)
split_f32(const float* __restrict__ in, __nv_bfloat16* __restrict__ h,
          __nv_bfloat16* __restrict__ l, int n4)
{
    int i = blockIdx.x * blockDim.x + threadIdx.x;
    if (i < n4) {
        float4 v = ((const float4*)in)[i];
        uint2 hi, lo;
        cvt_split(v, hi, lo);
        ((uint2*)h)[i] = hi;
        ((uint2*)l)[i] = lo;
    }
}

// ================= pre-split GEMM, single-sync cp.async pipeline =================
#define ROWB    80
#define PLANE_B (128 * ROWB)      // 10240
#define BUF_B   (4 * PLANE_B)     // 40960
#define GEMM_SMEM (2 * BUF_B)     // 81920 -> 2 CTAs/SM

template<bool SPLIT_OUT>
__global__ void __launch_bounds__(256, 2)
gemm_pre(const __nv_bfloat16* __restrict__ Ah, const __nv_bfloat16* __restrict__ Al,
         const __nv_bfloat16* __restrict__ Wh, const __nv_bfloat16* __restrict__ Wl,
         const float* __restrict__ bias,
         float* __restrict__ Cf,
         __nv_bfloat16* __restrict__ Ch, __nv_bfloat16* __restrict__ Cl,
         int M, int N, int K, int qcols, float qscale)
{
    extern __shared__ __align__(128) char smem[];
    const uint32_t sb = smem_u32(smem);
    const int tid = threadIdx.x;
    const int lane = tid & 31, wid = tid >> 5;
    const int wm = wid >> 1, wn = wid & 1;
    const int m0 = blockIdx.y * 128;
    const int n0 = blockIdx.x * 128;

    float acc[2][8][4] = {};

    const int frow = lane & 15;
    const int fcol = ((lane >> 4) & 1) * 16;
    uint32_t a_addr[2], b_addr[4];
    #pragma unroll
    for (int mt = 0; mt < 2; mt++)
        a_addr[mt] = (uint32_t)((wm * 32 + mt * 16 + frow) * ROWB + fcol);
    #pragma unroll
    for (int p = 0; p < 4; p++)
        b_addr[p] = (uint32_t)((wn * 64 + p * 16 + frow) * ROWB + fcol);

    auto issue = [&](int stage, int k0) {
        const uint32_t sbuf = sb + stage * BUF_B;
        #pragma unroll
        for (int j = 0; j < 2; j++) {
            int cid = tid + j * 256;
            int r = cid >> 2, c16 = cid & 3;
            uint32_t so = (uint32_t)(r * ROWB + c16 * 16);
            size_t ga = (size_t)(m0 + r) * K + k0 + c16 * 8;
            size_t gb = (size_t)(n0 + r) * K + k0 + c16 * 8;
            CP16(sbuf + 0 * PLANE_B + so, Ah + ga);
            CP16(sbuf + 1 * PLANE_B + so, Al + ga);
            CP16(sbuf + 2 * PLANE_B + so, Wh + gb);
            CP16(sbuf + 3 * PLANE_B + so, Wl + gb);
        }
        CP_COMMIT();
    };

    const int nch = K / 32;
    issue(0, 0);

    for (int i = 0; i < nch; i++) {
        CP_WAIT0();            // stage i landed
        __syncthreads();       // all warps done computing stage i-1
        if (i + 1 < nch) issue((i + 1) & 1, (i + 1) * 32);

        const uint32_t base = sb + (i & 1) * BUF_B;
        #pragma unroll
        for (int kh = 0; kh < 2; kh++) {
            const uint32_t kb = kh * 32;
            uint32_t ah[2][4], av[2][4], bb[4][4];
            #pragma unroll
            for (int mt = 0; mt < 2; mt++) {
                ldm_x4(ah[mt], base + 0 * PLANE_B + a_addr[mt] + kb);
                ldm_x4(av[mt], base + 1 * PLANE_B + a_addr[mt] + kb);
            }
            // ---- bb = B_hi ----
            #pragma unroll
            for (int p = 0; p < 4; p++)
                ldm_x4(bb[p], base + 2 * PLANE_B + b_addr[p] + kb);
            #pragma unroll
            for (int mt = 0; mt < 2; mt++)
                #pragma unroll
                for (int p = 0; p < 4; p++) {
                    uint32_t b0[2] = { bb[p][0], bb[p][2] };
                    uint32_t b1[2] = { bb[p][1], bb[p][3] };
                    mma16816(acc[mt][2*p+0], ah[mt], b0);
                    mma16816(acc[mt][2*p+1], ah[mt], b1);
                }
            #pragma unroll
            for (int mt = 0; mt < 2; mt++)
                #pragma unroll
                for (int p = 0; p < 4; p++) {
                    uint32_t b0[2] = { bb[p][0], bb[p][2] };
                    uint32_t b1[2] = { bb[p][1], bb[p][3] };
                    mma16816(acc[mt][2*p+0], av[mt], b0);
                    mma16816(acc[mt][2*p+1], av[mt], b1);
                }
            // ---- bb = B_lo (reuse regs) ----
            #pragma unroll
            for (int p = 0; p < 4; p++)
                ldm_x4(bb[p], base + 3 * PLANE_B + b_addr[p] + kb);
            #pragma unroll
            for (int mt = 0; mt < 2; mt++)
                #pragma unroll
                for (int p = 0; p < 4; p++) {
                    uint32_t b0[2] = { bb[p][0], bb[p][2] };
                    uint32_t b1[2] = { bb[p][1], bb[p][3] };
                    mma16816(acc[mt][2*p+0], ah[mt], b0);
                    mma16816(acc[mt][2*p+1], ah[mt], b1);
                }
        }
    }

    // epilogue
    const int g = lane >> 2, t = lane & 3;
    #pragma unroll
    for (int mt = 0; mt < 2; mt++) {
        int row = m0 + wm * 32 + mt * 16 + g;
        #pragma unroll
        for (int nt = 0; nt < 8; nt++) {
            int col = n0 + wn * 64 + nt * 8 + t * 2;
            float bx = bias[col], by = bias[col + 1];
            float* c = acc[mt][nt];
            float v0 = c[0] + bx, v1 = c[1] + by;
            float v2 = c[2] + bx, v3 = c[3] + by;
            if (SPLIT_OUT) {
                float s = (col < qcols) ? qscale : 1.0f;
                uint32_t h0, l0, h1, l1;
                split2(v0 * s, v1 * s, h0, l0);
                split2(v2 * s, v3 * s, h1, l1);
                *(uint32_t*)&Ch[(size_t)row * N + col] = h0;
                *(uint32_t*)&Cl[(size_t)row * N + col] = l0;
                *(uint32_t*)&Ch[(size_t)(row + 8) * N + col] = h1;
                *(uint32_t*)&Cl[(size_t)(row + 8) * N + col] = l1;
            } else {
                *(float2*)(Cf + (size_t)row * N + col) = make_float2(v0, v1);
                *(float2*)(Cf + (size_t)(row + 8) * N + col) = make_float2(v2, v3);
            }
        }
    }
}

// ================= HMMA flash attention: cp.async double-buffered KV =================
// CTA = 128 queries of one (b,h); 32 key tiles of 64. 8 warps, warp-local softmax.
#define KSTR 144
#define KV_PL   (64 * KSTR)                  // 9216 per plane
#define KV_B    (4 * KV_PL)                  // 36864 per stage
#define AQH 0
#define AQL (128 * KSTR)                     // 18432
#define AKV (2 * 128 * KSTR)                 // 36864
#define ATT_SMEM (AKV + 2 * KV_B)            // 110592 -> 2 CTAs/SM

__global__ void __launch_bounds__(256, 2)
attn_pre(const __nv_bfloat16* __restrict__ qkvh,
         const __nv_bfloat16* __restrict__ qkvl,
         __nv_bfloat16* __restrict__ atth,
         __nv_bfloat16* __restrict__ attl)
{
    extern __shared__ __align__(128) char smem[];
    const uint32_t sb = smem_u32(smem);
    const int tid = threadIdx.x;
    const int lane = tid & 31, wid = tid >> 5;
    const int b = blockIdx.y >> 4, h = blockIdx.y & 15;
    const int q0 = blockIdx.x * 128;

    const size_t rs = 3 * EMB;
    const __nv_bfloat16* Qh = qkvh + (size_t)(b * SEQ) * rs + h * HD;
    const __nv_bfloat16* Ql = qkvl + (size_t)(b * SEQ) * rs + h * HD;
    const __nv_bfloat16* Kh = Qh + EMB;
    const __nv_bfloat16* Kl = Ql + EMB;
    const __nv_bfloat16* Vh = Qh + 2 * EMB;
    const __nv_bfloat16* Vl = Ql + 2 * EMB;

    auto issueKV = [&](int stage, int k0) {
        const uint32_t sbuf = sb + AKV + stage * KV_B;
        #pragma unroll
        for (int i = 0; i < 2; i++) {
            int idx = tid + i * 256;           // 0..511
            int r = idx >> 3, c16 = idx & 7;
            size_t go = (size_t)(k0 + r) * rs + c16 * 8;
            uint32_t so = (uint32_t)(r * KSTR + c16 * 16);
            CP16(sbuf + 0 * KV_PL + so, Kh + go);
            CP16(sbuf + 1 * KV_PL + so, Kl + go);
            CP16(sbuf + 2 * KV_PL + so, Vh + go);
            CP16(sbuf + 3 * KV_PL + so, Vl + go);
        }
        CP_COMMIT();
    };

    issueKV(0, 0);

    // ---- load Q tile (sync; once) ----
    #pragma unroll
    for (int i = 0; i < 4; i++) {
        int idx = tid + i * 256;
        int r = idx >> 3, c16 = idx & 7;
        size_t go = (size_t)(q0 + r) * rs + c16 * 8;
        uint32_t so = r * KSTR + c16 * 16;
        *(uint4*)(smem + AQH + so) = *(const uint4*)(Qh + go);
        *(uint4*)(smem + AQL + so) = *(const uint4*)(Ql + go);
    }

    const int frow = lane & 15;
    const int fcol = ((lane >> 4) & 1) * 16;
    const uint32_t qa = sb + AQH + (uint32_t)((wid * 16 + frow) * KSTR + fcol);
    const uint32_t kvf = (uint32_t)(frow * KSTR + fcol);
    const uint32_t QLO = AQL - AQH;

    float oacc[8][4] = {};
    float m0 = -1e30f, m1 = -1e30f;
    float l0 = 0.0f, l1 = 0.0f;

    for (int kt = 0; kt < SEQ / 64; kt++) {
        CP_WAIT0();            // KV stage kt landed
        __syncthreads();       // all warps done with stage kt-1 (and Q stores on kt=0)
        if (kt + 1 < SEQ / 64) issueKV((kt + 1) & 1, (kt + 1) * 64);

        const uint32_t base = sb + AKV + (kt & 1) * KV_B;
        const uint32_t ka = base + 0 * KV_PL + kvf;
        const uint32_t kaL = base + 1 * KV_PL + kvf;
        const uint32_t va = base + 2 * KV_PL + kvf;
        const uint32_t vaL = base + 3 * KV_PL + kvf;

        // ---- S = Q @ K^T (16 x 64 per warp) ----
        float sacc[8][4] = {};
        #pragma unroll
        for (int kk = 0; kk < 4; kk++) {
            uint32_t aqh[4], aql[4], kf[4][4];
            ldm_x4(aqh, qa + kk * 32);
            ldm_x4(aql, qa + QLO + kk * 32);
            #pragma unroll
            for (int p = 0; p < 4; p++)
                ldm_x4(kf[p], ka + p * (16 * KSTR) + kk * 32);
            #pragma unroll
            for (int p = 0; p < 4; p++) {
                uint32_t b0[2] = { kf[p][0], kf[p][2] };
                uint32_t b1[2] = { kf[p][1], kf[p][3] };
                mma16816(sacc[2*p+0], aqh, b0);
                mma16816(sacc[2*p+1], aqh, b1);
            }
            #pragma unroll
            for (int p = 0; p < 4; p++) {
                uint32_t b0[2] = { kf[p][0], kf[p][2] };
                uint32_t b1[2] = { kf[p][1], kf[p][3] };
                mma16816(sacc[2*p+0], aql, b0);
                mma16816(sacc[2*p+1], aql, b1);
            }
            #pragma unroll
            for (int p = 0; p < 4; p++)
                ldm_x4(kf[p], kaL + p * (16 * KSTR) + kk * 32);
            #pragma unroll
            for (int p = 0; p < 4; p++) {
                uint32_t b0[2] = { kf[p][0], kf[p][2] };
                uint32_t b1[2] = { kf[p][1], kf[p][3] };
                mma16816(sacc[2*p+0], aqh, b0);
                mma16816(sacc[2*p+1], aqh, b1);
            }
        }

        // ---- online softmax (base-2, warp-local) ----
        float mx0 = -1e30f, mx1 = -1e30f;
        #pragma unroll
        for (int nt = 0; nt < 8; nt++) {
            mx0 = fmaxf(mx0, fmaxf(sacc[nt][0], sacc[nt][1]));
            mx1 = fmaxf(mx1, fmaxf(sacc[nt][2], sacc[nt][3]));
        }
        mx0 = fmaxf(mx0, __shfl_xor_sync(0xffffffffu, mx0, 1));
        mx0 = fmaxf(mx0, __shfl_xor_sync(0xffffffffu, mx0, 2));
        mx1 = fmaxf(mx1, __shfl_xor_sync(0xffffffffu, mx1, 1));
        mx1 = fmaxf(mx1, __shfl_xor_sync(0xffffffffu, mx1, 2));
        float mn0 = fmaxf(m0, mx0), mn1 = fmaxf(m1, mx1);
        float a0 = exp2f(m0 - mn0), a1 = exp2f(m1 - mn1);
        m0 = mn0; m1 = mn1;

        float ls0 = 0.0f, ls1 = 0.0f;
        #pragma unroll
        for (int nt = 0; nt < 8; nt++) {
            sacc[nt][0] = exp2f(sacc[nt][0] - mn0);
            sacc[nt][1] = exp2f(sacc[nt][1] - mn0);
            sacc[nt][2] = exp2f(sacc[nt][2] - mn1);
            sacc[nt][3] = exp2f(sacc[nt][3] - mn1);
            ls0 += sacc[nt][0] + sacc[nt][1];
            ls1 += sacc[nt][2] + sacc[nt][3];
        }
        l0 = l0 * a0 + ls0;
        l1 = l1 * a1 + ls1;
        #pragma unroll
        for (int nt = 0; nt < 8; nt++) {
            oacc[nt][0] *= a0; oacc[nt][1] *= a0;
            oacc[nt][2] *= a1; oacc[nt][3] *= a1;
        }

        // ---- O += P @ V (V via ldmatrix.trans; reuse V regs) ----
        #pragma unroll
        for (int kk = 0; kk < 4; kk++) {
            uint32_t ph[4], pl[4], vf[4][4];
            split2(sacc[2*kk  ][0], sacc[2*kk  ][1], ph[0], pl[0]);
            split2(sacc[2*kk  ][2], sacc[2*kk  ][3], ph[1], pl[1]);
            split2(sacc[2*kk+1][0], sacc[2*kk+1][1], ph[2], pl[2]);
            split2(sacc[2*kk+1][2], sacc[2*kk+1][3], ph[3], pl[3]);
            #pragma unroll
            for (int nd = 0; nd < 4; nd++)
                ldm_x4_t(vf[nd], va + kk * (16 * KSTR) + nd * 32);
            #pragma unroll
            for (int nd = 0; nd < 4; nd++) {
                uint32_t b0[2] = { vf[nd][0], vf[nd][1] };
                uint32_t b1[2] = { vf[nd][2], vf[nd][3] };
                mma16816(oacc[2*nd+0], ph, b0);
                mma16816(oacc[2*nd+1], ph, b1);
            }
            #pragma unroll
            for (int nd = 0; nd < 4; nd++) {
                uint32_t b0[2] = { vf[nd][0], vf[nd][1] };
                uint32_t b1[2] = { vf[nd][2], vf[nd][3] };
                mma16816(oacc[2*nd+0], pl, b0);
                mma16816(oacc[2*nd+1], pl, b1);
            }
            #pragma unroll
            for (int nd = 0; nd < 4; nd++)
                ldm_x4_t(vf[nd], vaL + kk * (16 * KSTR) + nd * 32);
            #pragma unroll
            for (int nd = 0; nd < 4; nd++) {
                uint32_t b0[2] = { vf[nd][0], vf[nd][1] };
                uint32_t b1[2] = { vf[nd][2], vf[nd][3] };
                mma16816(oacc[2*nd+0], ph, b0);
                mma16816(oacc[2*nd+1], ph, b1);
            }
        }
    }

    // ---- finalize ----
    l0 += __shfl_xor_sync(0xffffffffu, l0, 1);
    l0 += __shfl_xor_sync(0xffffffffu, l0, 2);
    l1 += __shfl_xor_sync(0xffffffffu, l1, 1);
    l1 += __shfl_xor_sync(0xffffffffu, l1, 2);
    float inv0 = 1.0f / l0, inv1 = 1.0f / l1;

    const int g = lane >> 2, t = lane & 3;
    const int row = q0 + wid * 16 + g;
    size_t o0 = (size_t)(b * SEQ + row) * EMB + h * HD;
    size_t o1 = (size_t)(b * SEQ + row + 8) * EMB + h * HD;
    #pragma unroll
    for (int nt = 0; nt < 8; nt++) {
        int col = nt * 8 + t * 2;
        uint32_t h0, lo0, h1, lo1;
        split2(oacc[nt][0] * inv0, oacc[nt][1] * inv0, h0, lo0);
        split2(oacc[nt][2] * inv1, oacc[nt][3] * inv1, h1, lo1);
        *(uint32_t*)&atth[o0 + col] = h0;
        *(uint32_t*)&attl[o0 + col] = lo0;
        *(uint32_t*)&atth[o1 + col] = h1;
        *(uint32_t*)&attl[o1 + col] = lo1;
    }
}

// ---------------------------------------------------------------------------
extern "C" void kernel_launch(void* const* d_in, const int* in_sizes, int n_in,
                              void* d_out, int out_size)
{
    const float* x      = (const float*)d_in[0];
    const float* w_qkv  = (const float*)d_in[1];
    const float* b_qkv  = (const float*)d_in[2];
    const float* w_proj = (const float*)d_in[3];
    const float* b_proj = (const float*)d_in[4];
    float* out = (float*)d_out;

    __nv_bfloat16 *xh, *xl, *wqh, *wql, *wph, *wpl, *qh, *ql, *ath, *atl;
    cudaGetSymbolAddress((void**)&xh, g_xh);
    cudaGetSymbolAddress((void**)&xl, g_xl);
    cudaGetSymbolAddress((void**)&wqh, g_wqh);
    cudaGetSymbolAddress((void**)&wql, g_wql);
    cudaGetSymbolAddress((void**)&wph, g_wph);
    cudaGetSymbolAddress((void**)&wpl, g_wpl);
    cudaGetSymbolAddress((void**)&qh, g_qkvh);
    cudaGetSymbolAddress((void**)&ql, g_qkvl);
    cudaGetSymbolAddress((void**)&ath, g_atth);
    cudaGetSymbolAddress((void**)&atl, g_attl);

    cudaFuncSetAttribute(gemm_pre<true>,  cudaFuncAttributeMaxDynamicSharedMemorySize, GEMM_SMEM);
    cudaFuncSetAttribute(gemm_pre<false>, cudaFuncAttributeMaxDynamicSharedMemorySize, GEMM_SMEM);
    cudaFuncSetAttribute(attn_pre, cudaFuncAttributeMaxDynamicSharedMemorySize, ATT_SMEM);

    // 0) pre-split operands
    {
        int n4 = TOK * EMB / 4;
        split_f32<<<(n4 + 255) / 256, 256>>>(x, xh, xl, n4);
        n4 = 3 * EMB * EMB / 4;
        split_f32<<<(n4 + 255) / 256, 256>>>(w_qkv, wqh, wql, n4);
        n4 = EMB * EMB / 4;
        split_f32<<<(n4 + 255) / 256, 256>>>(w_proj, wph, wpl, n4);
    }

    const float QSCALE = 0.125f * 1.4426950408889634f;   // 1/sqrt(64) * log2(e)

    // 1) QKV projection -> split bf16 qkv (Q columns pre-scaled)
    dim3 g1(3 * EMB / 128, TOK / 128);
    gemm_pre<true><<<g1, 256, GEMM_SMEM>>>(xh, xl, wqh, wql, b_qkv,
                                           nullptr, qh, ql,
                                           TOK, 3 * EMB, EMB, EMB, QSCALE);

    // 2) Attention -> split bf16 att
    dim3 g2(SEQ / 128, BATCH * NH);
    attn_pre<<<g2, 256, ATT_SMEM>>>(qh, ql, ath, atl);

    // 3) Output projection -> fp32 out
    dim3 g3(EMB / 128, TOK / 128);
    gemm_pre<false><<<g3, 256, GEMM_SMEM>>>(ath, atl, wph, wpl, b_proj,
                                            out, nullptr, nullptr,
                                            TOK, EMB, EMB, 0, 1.0f);
}

// round 9
// speedup vs baseline: 3.0041x; 1.0205x over previous
#include <cuda_runtime.h>
#include <cuda_bf16.h>
#include <cstdint>

#define BATCH 4
#define SEQ   2048
#define EMB   1024
#define NH    16
#define HD    64
#define TOK   (BATCH*SEQ)      // 8192

// ---------------- scratch (device globals; allocation-free rule) ----------
__device__ __nv_bfloat16 g_xh[(size_t)TOK * EMB];
__device__ __nv_bfloat16 g_xl[(size_t)TOK * EMB];
__device__ __nv_bfloat16 g_wqh[(size_t)3 * EMB * EMB];
__device__ __nv_bfloat16 g_wql[(size_t)3 * EMB * EMB];
__device__ __nv_bfloat16 g_wph[(size_t)EMB * EMB];
__device__ __nv_bfloat16 g_wpl[(size_t)EMB * EMB];
__device__ __nv_bfloat16 g_qkvh[(size_t)TOK * 3 * EMB];
__device__ __nv_bfloat16 g_qkvl[(size_t)TOK * 3 * EMB];
__device__ __nv_bfloat16 g_atth[(size_t)TOK * EMB];
__device__ __nv_bfloat16 g_attl[(size_t)TOK * EMB];

// ---------------- primitives ----------------
__device__ __forceinline__ uint32_t smem_u32(const void* p) {
    uint32_t a;
    asm("{ .reg .u64 t; cvta.to.shared.u64 t, %1; cvt.u32.u64 %0, t; }" : "=r"(a) : "l"(p));
    return a;
}
__device__ __forceinline__ void ldm_x4(uint32_t* r, uint32_t addr) {
    asm volatile("ldmatrix.sync.aligned.m8n8.x4.shared.b16 {%0,%1,%2,%3}, [%4];"
        : "=r"(r[0]), "=r"(r[1]), "=r"(r[2]), "=r"(r[3]) : "r"(addr));
}
__device__ __forceinline__ void ldm_x4_t(uint32_t* r, uint32_t addr) {
    asm volatile("ldmatrix.sync.aligned.m8n8.x4.trans.shared.b16 {%0,%1,%2,%3}, [%4];"
        : "=r"(r[0]), "=r"(r[1]), "=r"(r[2]), "=r"(r[3]) : "r"(addr));
}
__device__ __forceinline__ void mma16816(float* c, const uint32_t* a, const uint32_t* b) {
    asm volatile(
        "mma.sync.aligned.m16n8k16.row.col.f32.bf16.bf16.f32 "
        "{%0,%1,%2,%3}, {%4,%5,%6,%7}, {%8,%9}, {%0,%1,%2,%3};"
        : "+f"(c[0]), "+f"(c[1]), "+f"(c[2]), "+f"(c[3])
        : "r"(a[0]), "r"(a[1]), "r"(a[2]), "r"(a[3]), "r"(b[0]), "r"(b[1]));
}
#define CP16(dst, src) \
    asm volatile("cp.async.cg.shared.global [%0], [%1], 16;" \
        :: "r"(dst), "l"(src) : "memory")
#define CP_COMMIT() asm volatile("cp.async.commit_group;" ::: "memory")
#define CP_WAIT0()  asm volatile("cp.async.wait_group 0;" ::: "memory")

__device__ __forceinline__ void cvt_split(float4 v, uint2& hi, uint2& lo) {
    __nv_bfloat162 h0 = __floats2bfloat162_rn(v.x, v.y);
    __nv_bfloat162 h1 = __floats2bfloat162_rn(v.z, v.w);
    float rx = __bfloat162float(h0.x), ry = __bfloat162float(h0.y);
    float rz = __bfloat162float(h1.x), rw = __bfloat162float(h1.y);
    __nv_bfloat162 l0 = __floats2bfloat162_rn(v.x - rx, v.y - ry);
    __nv_bfloat162 l1 = __floats2bfloat162_rn(v.z - rz, v.w - rw);
    hi.x = *(uint32_t*)&h0; hi.y = *(uint32_t*)&h1;
    lo.x = *(uint32_t*)&l0; lo.y = *(uint32_t*)&l1;
}
__device__ __forceinline__ void split2(float x, float y, uint32_t& h, uint32_t& l) {
    __nv_bfloat162 hh = __floats2bfloat162_rn(x, y);
    h = *(uint32_t*)&hh;
    __nv_bfloat162 ll = __floats2bfloat162_rn(x - __bfloat162float(hh.x),
                                              y - __bfloat162float(hh.y));
    l = *(uint32_t*)&ll;
}

// ---------------- fp32 -> split bf16 planes ----------------
__global__ void __launch_bounds__(256)
split_f32(const float* __restrict__ in, __nv_bfloat16* __restrict__ h,
          __nv_bfloat16* __restrict__ l, int n4)
{
    int i = blockIdx.x * blockDim.x + threadIdx.x;
    if (i < n4) {
        float4 v = ((const float4*)in)[i];
        uint2 hi, lo;
        cvt_split(v, hi, lo);
        ((uint2*)h)[i] = hi;
        ((uint2*)l)[i] = lo;
    }
}

// ================= pre-split GEMM, fragment-pipelined, 1 CTA/SM =================
#define ROWB    80
#define PLANE_B (128 * ROWB)      // 10240
#define BUF_B   (4 * PLANE_B)     // 40960
#define GEMM_SMEM (2 * BUF_B)     // 81920

__device__ __forceinline__ void mma_block(float acc[2][8][4],
        const uint32_t a[2][4], const uint32_t b[4][4]) {
    #pragma unroll
    for (int mt = 0; mt < 2; mt++)
        #pragma unroll
        for (int p = 0; p < 4; p++) {
            uint32_t b0[2] = { b[p][0], b[p][2] };
            uint32_t b1[2] = { b[p][1], b[p][3] };
            mma16816(acc[mt][2*p+0], a[mt], b0);
            mma16816(acc[mt][2*p+1], a[mt], b1);
        }
}

template<bool SPLIT_OUT>
__global__ void __launch_bounds__(256)
gemm_pre(const __nv_bfloat16* __restrict__ Ah, const __nv_bfloat16* __restrict__ Al,
         const __nv_bfloat16* __restrict__ Wh, const __nv_bfloat16* __restrict__ Wl,
         const float* __restrict__ bias,
         float* __restrict__ Cf,
         __nv_bfloat16* __restrict__ Ch, __nv_bfloat16* __restrict__ Cl,
         int M, int N, int K, int qcols, float qscale)
{
    extern __shared__ __align__(128) char smem[];
    const uint32_t sb = smem_u32(smem);
    const int tid = threadIdx.x;
    const int lane = tid & 31, wid = tid >> 5;
    const int wm = wid >> 1, wn = wid & 1;
    const int m0 = blockIdx.y * 128;
    const int n0 = blockIdx.x * 128;

    float acc[2][8][4] = {};

    const int frow = lane & 15;
    const int fcol = ((lane >> 4) & 1) * 16;
    uint32_t a_addr[2], b_addr[4];
    #pragma unroll
    for (int mt = 0; mt < 2; mt++)
        a_addr[mt] = (uint32_t)((wm * 32 + mt * 16 + frow) * ROWB + fcol);
    #pragma unroll
    for (int p = 0; p < 4; p++)
        b_addr[p] = (uint32_t)((wn * 64 + p * 16 + frow) * ROWB + fcol);

    auto issue = [&](int stage, int k0) {
        const uint32_t sbuf = sb + stage * BUF_B;
        #pragma unroll
        for (int j = 0; j < 2; j++) {
            int cid = tid + j * 256;
            int r = cid >> 2, c16 = cid & 3;
            uint32_t so = (uint32_t)(r * ROWB + c16 * 16);
            size_t ga = (size_t)(m0 + r) * K + k0 + c16 * 8;
            size_t gb = (size_t)(n0 + r) * K + k0 + c16 * 8;
            CP16(sbuf + 0 * PLANE_B + so, Ah + ga);
            CP16(sbuf + 1 * PLANE_B + so, Al + ga);
            CP16(sbuf + 2 * PLANE_B + so, Wh + gb);
            CP16(sbuf + 3 * PLANE_B + so, Wl + gb);
        }
        CP_COMMIT();
    };

    const int nch = K / 32;
    issue(0, 0);

    for (int i = 0; i < nch; i++) {
        CP_WAIT0();            // stage i landed
        __syncthreads();       // everyone done with stage i-1
        const uint32_t base = sb + (i & 1) * BUF_B;

        uint32_t a0h[2][4], a0l[2][4], b0h[4][4], b0l[4][4];
        uint32_t a1h[2][4], a1l[2][4], b1h[4][4], b1l[4][4];

        // fragments for kh=0 (hh operands first)
        #pragma unroll
        for (int mt = 0; mt < 2; mt++) {
            ldm_x4(a0h[mt], base + 0 * PLANE_B + a_addr[mt]);
            ldm_x4(a0l[mt], base + 1 * PLANE_B + a_addr[mt]);
        }
        #pragma unroll
        for (int p = 0; p < 4; p++)
            ldm_x4(b0h[p], base + 2 * PLANE_B + b_addr[p]);

        if (i + 1 < nch) issue((i + 1) & 1, (i + 1) * 32);

        // prefetch Bl(0) under hh(0)
        #pragma unroll
        for (int p = 0; p < 4; p++)
            ldm_x4(b0l[p], base + 3 * PLANE_B + b_addr[p]);

        mma_block(acc, a0h, b0h);      // hh(0)

        // prefetch A(1), Bh(1) under lh(0)/hl(0)
        #pragma unroll
        for (int mt = 0; mt < 2; mt++) {
            ldm_x4(a1h[mt], base + 0 * PLANE_B + a_addr[mt] + 32);
            ldm_x4(a1l[mt], base + 1 * PLANE_B + a_addr[mt] + 32);
        }
        #pragma unroll
        for (int p = 0; p < 4; p++)
            ldm_x4(b1h[p], base + 2 * PLANE_B + b_addr[p] + 32);

        mma_block(acc, a0l, b0h);      // lh(0)
        mma_block(acc, a0h, b0l);      // hl(0)

        // prefetch Bl(1) under hh(1)
        #pragma unroll
        for (int p = 0; p < 4; p++)
            ldm_x4(b1l[p], base + 3 * PLANE_B + b_addr[p] + 32);

        mma_block(acc, a1h, b1h);      // hh(1)
        mma_block(acc, a1l, b1h);      // lh(1)
        mma_block(acc, a1h, b1l);      // hl(1)
    }

    // epilogue
    const int g = lane >> 2, t = lane & 3;
    #pragma unroll
    for (int mt = 0; mt < 2; mt++) {
        int row = m0 + wm * 32 + mt * 16 + g;
        #pragma unroll
        for (int nt = 0; nt < 8; nt++) {
            int col = n0 + wn * 64 + nt * 8 + t * 2;
            float bx = bias[col], by = bias[col + 1];
            float* c = acc[mt][nt];
            float v0 = c[0] + bx, v1 = c[1] + by;
            float v2 = c[2] + bx, v3 = c[3] + by;
            if (SPLIT_OUT) {
                float s = (col < qcols) ? qscale : 1.0f;
                uint32_t h0, l0, h1, l1;
                split2(v0 * s, v1 * s, h0, l0);
                split2(v2 * s, v3 * s, h1, l1);
                *(uint32_t*)&Ch[(size_t)row * N + col] = h0;
                *(uint32_t*)&Cl[(size_t)row * N + col] = l0;
                *(uint32_t*)&Ch[(size_t)(row + 8) * N + col] = h1;
                *(uint32_t*)&Cl[(size_t)(row + 8) * N + col] = l1;
            } else {
                *(float2*)(Cf + (size_t)row * N + col) = make_float2(v0, v1);
                *(float2*)(Cf + (size_t)(row + 8) * N + col) = make_float2(v2, v3);
            }
        }
    }
}

// ================= HMMA flash attention: cp.async double-buffered KV =================
// (unchanged from round 8 — known-good)
#define KSTR 144
#define KV_PL   (64 * KSTR)                  // 9216 per plane
#define KV_B    (4 * KV_PL)                  // 36864 per stage
#define AQH 0
#define AQL (128 * KSTR)                     // 18432
#define AKV (2 * 128 * KSTR)                 // 36864
#define ATT_SMEM (AKV + 2 * KV_B)            // 110592 -> 2 CTAs/SM

__global__ void __launch_bounds__(256, 2)
attn_pre(const __nv_bfloat16* __restrict__ qkvh,
         const __nv_bfloat16* __restrict__ qkvl,
         __nv_bfloat16* __restrict__ atth,
         __nv_bfloat16* __restrict__ attl)
{
    extern __shared__ __align__(128) char smem[];
    const uint32_t sb = smem_u32(smem);
    const int tid = threadIdx.x;
    const int lane = tid & 31, wid = tid >> 5;
    const int b = blockIdx.y >> 4, h = blockIdx.y & 15;
    const int q0 = blockIdx.x * 128;

    const size_t rs = 3 * EMB;
    const __nv_bfloat16* Qh = qkvh + (size_t)(b * SEQ) * rs + h * HD;
    const __nv_bfloat16* Ql = qkvl + (size_t)(b * SEQ) * rs + h * HD;
    const __nv_bfloat16* Kh = Qh + EMB;
    const __nv_bfloat16* Kl = Ql + EMB;
    const __nv_bfloat16* Vh = Qh + 2 * EMB;
    const __nv_bfloat16* Vl = Ql + 2 * EMB;

    auto issueKV = [&](int stage, int k0) {
        const uint32_t sbuf = sb + AKV + stage * KV_B;
        #pragma unroll
        for (int i = 0; i < 2; i++) {
            int idx = tid + i * 256;           // 0..511
            int r = idx >> 3, c16 = idx & 7;
            size_t go = (size_t)(k0 + r) * rs + c16 * 8;
            uint32_t so = (uint32_t)(r * KSTR + c16 * 16);
            CP16(sbuf + 0 * KV_PL + so, Kh + go);
            CP16(sbuf + 1 * KV_PL + so, Kl + go);
            CP16(sbuf + 2 * KV_PL + so, Vh + go);
            CP16(sbuf + 3 * KV_PL + so, Vl + go);
        }
        CP_COMMIT();
    };

    issueKV(0, 0);

    // ---- load Q tile (sync; once) ----
    #pragma unroll
    for (int i = 0; i < 4; i++) {
        int idx = tid + i * 256;
        int r = idx >> 3, c16 = idx & 7;
        size_t go = (size_t)(q0 + r) * rs + c16 * 8;
        uint32_t so = r * KSTR + c16 * 16;
        *(uint4*)(smem + AQH + so) = *(const uint4*)(Qh + go);
        *(uint4*)(smem + AQL + so) = *(const uint4*)(Ql + go);
    }

    const int frow = lane & 15;
    const int fcol = ((lane >> 4) & 1) * 16;
    const uint32_t qa = sb + AQH + (uint32_t)((wid * 16 + frow) * KSTR + fcol);
    const uint32_t kvf = (uint32_t)(frow * KSTR + fcol);
    const uint32_t QLO = AQL - AQH;

    float oacc[8][4] = {};
    float m0 = -1e30f, m1 = -1e30f;
    float l0 = 0.0f, l1 = 0.0f;

    for (int kt = 0; kt < SEQ / 64; kt++) {
        CP_WAIT0();
        __syncthreads();
        if (kt + 1 < SEQ / 64) issueKV((kt + 1) & 1, (kt + 1) * 64);

        const uint32_t base = sb + AKV + (kt & 1) * KV_B;
        const uint32_t ka = base + 0 * KV_PL + kvf;
        const uint32_t kaL = base + 1 * KV_PL + kvf;
        const uint32_t va = base + 2 * KV_PL + kvf;
        const uint32_t vaL = base + 3 * KV_PL + kvf;

        // ---- S = Q @ K^T (16 x 64 per warp) ----
        float sacc[8][4] = {};
        #pragma unroll
        for (int kk = 0; kk < 4; kk++) {
            uint32_t aqh[4], aql[4], kf[4][4];
            ldm_x4(aqh, qa + kk * 32);
            ldm_x4(aql, qa + QLO + kk * 32);
            #pragma unroll
            for (int p = 0; p < 4; p++)
                ldm_x4(kf[p], ka + p * (16 * KSTR) + kk * 32);
            #pragma unroll
            for (int p = 0; p < 4; p++) {
                uint32_t b0[2] = { kf[p][0], kf[p][2] };
                uint32_t b1[2] = { kf[p][1], kf[p][3] };
                mma16816(sacc[2*p+0], aqh, b0);
                mma16816(sacc[2*p+1], aqh, b1);
            }
            #pragma unroll
            for (int p = 0; p < 4; p++) {
                uint32_t b0[2] = { kf[p][0], kf[p][2] };
                uint32_t b1[2] = { kf[p][1], kf[p][3] };
                mma16816(sacc[2*p+0], aql, b0);
                mma16816(sacc[2*p+1], aql, b1);
            }
            #pragma unroll
            for (int p = 0; p < 4; p++)
                ldm_x4(kf[p], kaL + p * (16 * KSTR) + kk * 32);
            #pragma unroll
            for (int p = 0; p < 4; p++) {
                uint32_t b0[2] = { kf[p][0], kf[p][2] };
                uint32_t b1[2] = { kf[p][1], kf[p][3] };
                mma16816(sacc[2*p+0], aqh, b0);
                mma16816(sacc[2*p+1], aqh, b1);
            }
        }

        // ---- online softmax (base-2, warp-local) ----
        float mx0 = -1e30f, mx1 = -1e30f;
        #pragma unroll
        for (int nt = 0; nt < 8; nt++) {
            mx0 = fmaxf(mx0, fmaxf(sacc[nt][0], sacc[nt][1]));
            mx1 = fmaxf(mx1, fmaxf(sacc[nt][2], sacc[nt][3]));
        }
        mx0 = fmaxf(mx0, __shfl_xor_sync(0xffffffffu, mx0, 1));
        mx0 = fmaxf(mx0, __shfl_xor_sync(0xffffffffu, mx0, 2));
        mx1 = fmaxf(mx1, __shfl_xor_sync(0xffffffffu, mx1, 1));
        mx1 = fmaxf(mx1, __shfl_xor_sync(0xffffffffu, mx1, 2));
        float mn0 = fmaxf(m0, mx0), mn1 = fmaxf(m1, mx1);
        float a0 = exp2f(m0 - mn0), a1 = exp2f(m1 - mn1);
        m0 = mn0; m1 = mn1;

        float ls0 = 0.0f, ls1 = 0.0f;
        #pragma unroll
        for (int nt = 0; nt < 8; nt++) {
            sacc[nt][0] = exp2f(sacc[nt][0] - mn0);
            sacc[nt][1] = exp2f(sacc[nt][1] - mn0);
            sacc[nt][2] = exp2f(sacc[nt][2] - mn1);
            sacc[nt][3] = exp2f(sacc[nt][3] - mn1);
            ls0 += sacc[nt][0] + sacc[nt][1];
            ls1 += sacc[nt][2] + sacc[nt][3];
        }
        l0 = l0 * a0 + ls0;
        l1 = l1 * a1 + ls1;
        #pragma unroll
        for (int nt = 0; nt < 8; nt++) {
            oacc[nt][0] *= a0; oacc[nt][1] *= a0;
            oacc[nt][2] *= a1; oacc[nt][3] *= a1;
        }

        // ---- O += P @ V (V via ldmatrix.trans; reuse V regs) ----
        #pragma unroll
        for (int kk = 0; kk < 4; kk++) {
            uint32_t ph[4], pl[4], vf[4][4];
            split2(sacc[2*kk  ][0], sacc[2*kk  ][1], ph[0], pl[0]);
            split2(sacc[2*kk  ][2], sacc[2*kk  ][3], ph[1], pl[1]);
            split2(sacc[2*kk+1][0], sacc[2*kk+1][1], ph[2], pl[2]);
            split2(sacc[2*kk+1][2], sacc[2*kk+1][3], ph[3], pl[3]);
            #pragma unroll
            for (int nd = 0; nd < 4; nd++)
                ldm_x4_t(vf[nd], va + kk * (16 * KSTR) + nd * 32);
            #pragma unroll
            for (int nd = 0; nd < 4; nd++) {
                uint32_t b0[2] = { vf[nd][0], vf[nd][1] };
                uint32_t b1[2] = { vf[nd][2], vf[nd][3] };
                mma16816(oacc[2*nd+0], ph, b0);
                mma16816(oacc[2*nd+1], ph, b1);
            }
            #pragma unroll
            for (int nd = 0; nd < 4; nd++) {
                uint32_t b0[2] = { vf[nd][0], vf[nd][1] };
                uint32_t b1[2] = { vf[nd][2], vf[nd][3] };
                mma16816(oacc[2*nd+0], pl, b0);
                mma16816(oacc[2*nd+1], pl, b1);
            }
            #pragma unroll
            for (int nd = 0; nd < 4; nd++)
                ldm_x4_t(vf[nd], vaL + kk * (16 * KSTR) + nd * 32);
            #pragma unroll
            for (int nd = 0; nd < 4; nd++) {
                uint32_t b0[2] = { vf[nd][0], vf[nd][1] };
                uint32_t b1[2] = { vf[nd][2], vf[nd][3] };
                mma16816(oacc[2*nd+0], ph, b0);
                mma16816(oacc[2*nd+1], ph, b1);
            }
        }
    }

    // ---- finalize ----
    l0 += __shfl_xor_sync(0xffffffffu, l0, 1);
    l0 += __shfl_xor_sync(0xffffffffu, l0, 2);
    l1 += __shfl_xor_sync(0xffffffffu, l1, 1);
    l1 += __shfl_xor_sync(0xffffffffu, l1, 2);
    float inv0 = 1.0f / l0, inv1 = 1.0f / l1;

    const int g = lane >> 2, t = lane & 3;
    const int row = q0 + wid * 16 + g;
    size_t o0 = (size_t)(b * SEQ + row) * EMB + h * HD;
    size_t o1 = (size_t)(b * SEQ + row + 8) * EMB + h * HD;
    #pragma unroll
    for (int nt = 0; nt < 8; nt++) {
        int col = nt * 8 + t * 2;
        uint32_t h0, lo0, h1, lo1;
        split2(oacc[nt][0] * inv0, oacc[nt][1] * inv0, h0, lo0);
        split2(oacc[nt][2] * inv1, oacc[nt][3] * inv1, h1, lo1);
        *(uint32_t*)&atth[o0 + col] = h0;
        *(uint32_t*)&attl[o0 + col] = lo0;
        *(uint32_t*)&atth[o1 + col] = h1;
        *(uint32_t*)&attl[o1 + col] = lo1;
    }
}

// ---------------------------------------------------------------------------
extern "C" void kernel_launch(void* const* d_in, const int* in_sizes, int n_in,
                              void* d_out, int out_size)
{
    const float* x      = (const float*)d_in[0];
    const float* w_qkv  = (const float*)d_in[1];
    const float* b_qkv  = (const float*)d_in[2];
    const float* w_proj = (const float*)d_in[3];
    const float* b_proj = (const float*)d_in[4];
    float* out = (float*)d_out;

    __nv_bfloat16 *xh, *xl, *wqh, *wql, *wph, *wpl, *qh, *ql, *ath, *atl;
    cudaGetSymbolAddress((void**)&xh, g_xh);
    cudaGetSymbolAddress((void**)&xl, g_xl);
    cudaGetSymbolAddress((void**)&wqh, g_wqh);
    cudaGetSymbolAddress((void**)&wql, g_wql);
    cudaGetSymbolAddress((void**)&wph, g_wph);
    cudaGetSymbolAddress((void**)&wpl, g_wpl);
    cudaGetSymbolAddress((void**)&qh, g_qkvh);
    cudaGetSymbolAddress((void**)&ql, g_qkvl);
    cudaGetSymbolAddress((void**)&ath, g_atth);
    cudaGetSymbolAddress((void**)&atl, g_attl);

    cudaFuncSetAttribute(gemm_pre<true>,  cudaFuncAttributeMaxDynamicSharedMemorySize, GEMM_SMEM);
    cudaFuncSetAttribute(gemm_pre<false>, cudaFuncAttributeMaxDynamicSharedMemorySize, GEMM_SMEM);
    cudaFuncSetAttribute(attn_pre, cudaFuncAttributeMaxDynamicSharedMemorySize, ATT_SMEM);

    // 0) pre-split operands
    {
        int n4 = TOK * EMB / 4;
        split_f32<<<(n4 + 255) / 256, 256>>>(x, xh, xl, n4);
        n4 = 3 * EMB * EMB / 4;
        split_f32<<<(n4 + 255) / 256, 256>>>(w_qkv, wqh, wql, n4);
        n4 = EMB * EMB / 4;
        split_f32<<<(n4 + 255) / 256, 256>>>(w_proj, wph, wpl, n4);
    }

    const float QSCALE = 0.125f * 1.4426950408889634f;   // 1/sqrt(64) * log2(e)

    // 1) QKV projection -> split bf16 qkv (Q columns pre-scaled)
    dim3 g1(3 * EMB / 128, TOK / 128);
    gemm_pre<true><<<g1, 256, GEMM_SMEM>>>(xh, xl, wqh, wql, b_qkv,
                                           nullptr, qh, ql,
                                           TOK, 3 * EMB, EMB, EMB, QSCALE);

    // 2) Attention -> split bf16 att
    dim3 g2(SEQ / 128, BATCH * NH);
    attn_pre<<<g2, 256, ATT_SMEM>>>(qh, ql, ath, atl);

    // 3) Output projection -> fp32 out
    dim3 g3(EMB / 128, TOK / 128);
    gemm_pre<false><<<g3, 256, GEMM_SMEM>>>(ath, atl, wph, wpl, b_proj,
                                            out, nullptr, nullptr,
                                            TOK, EMB, EMB, 0, 1.0f);
}